// round 1
// baseline (speedup 1.0000x reference)
#include <cuda_runtime.h>
#include <cuda_bf16.h>
#include <math.h>

#define NN   50000      // real nodes
#define NV   50001      // nodes + virtual node
#define NE   400000     // original edges
#define IND  256        // input dim
#define HID  128        // hidden dim
#define NH   2          // heads
#define C2   256        // NH*HID (gemm cols for layers)
#define OD   64         // output dim
#define VPART_BLOCKS 112

// ---------------- scratch (static device allocations; no cudaMalloc) --------
__device__ float g_x0[NV * IND];          // layer-0 input (X + vnode row)
__device__ float g_h[NV * C2];            // per-layer transformed features [node][head*128+o]
__device__ float g_xa[NV * HID];          // ping buffer
__device__ float g_xb[NV * HID];          // pong buffer
__device__ float g_as[NV * NH];           // alpha_src per node/head
__device__ float g_ad[NV * NH];           // alpha_dst per node/head
__device__ int   g_cnt[NV];
__device__ int   g_cur[NV];
__device__ int   g_rowptr[NV + 1];
__device__ int   g_srcsorted[NE];         // src ids sorted by dst (CSR)
__device__ float g_colsum[IND];
__device__ float g_vmaxpart[VPART_BLOCKS * NH];
__device__ float g_vred[NH];              // vnode softmax max per head
__device__ float g_vS[C2];                // vnode weighted-sum accumulator
__device__ float g_vden[NH];              // vnode softmax denom per head

__device__ __forceinline__ float lrelu(float x) { return x > 0.f ? x : 0.2f * x; }

// ---------------- misc init -------------------------------------------------
__global__ void k_zero() {
    int i = blockIdx.x * blockDim.x + threadIdx.x;
    int stride = gridDim.x * blockDim.x;
    for (int j = i; j < NV; j += stride) { g_cnt[j] = 0; g_cur[j] = 0; }
    if (i < IND) g_colsum[i] = 0.f;
}

__global__ void k_copyX(const float* __restrict__ X) {
    int i = blockIdx.x * blockDim.x + threadIdx.x;
    int stride = gridDim.x * blockDim.x;
    const float4* src = reinterpret_cast<const float4*>(X);
    float4* dst = reinterpret_cast<float4*>(g_x0);
    int n4 = NN * IND / 4;
    for (int j = i; j < n4; j += stride) dst[j] = src[j];
}

__global__ void k_colsum(const float* __restrict__ X) {
    int c = threadIdx.x;                  // 256 = IND
    float s = 0.f;
    for (int r = blockIdx.x; r < NN; r += gridDim.x)
        s += X[r * IND + c];
    atomicAdd(&g_colsum[c], s);
}

__global__ void k_vrow() {
    int c = threadIdx.x;
    g_x0[NN * IND + c] = g_colsum[c] * (1.0f / NN);
}

// ---------------- CSR build -------------------------------------------------
__global__ void k_hist(const int* __restrict__ ei) {
    int i = blockIdx.x * blockDim.x + threadIdx.x;
    int stride = gridDim.x * blockDim.x;
    for (int e = i; e < NE; e += stride)
        atomicAdd(&g_cnt[ei[NE + e]], 1);
}

__global__ void k_scan() {           // 1 block, 1024 threads
    __shared__ int s[1024];
    int t = threadIdx.x;
    const int CH = (NV + 1023) / 1024;     // 49
    int base = t * CH;
    int acc = 0;
    for (int i = 0; i < CH; i++) { int idx = base + i; if (idx < NV) acc += g_cnt[idx]; }
    s[t] = acc;
    __syncthreads();
    for (int off = 1; off < 1024; off <<= 1) {
        int v = (t >= off) ? s[t - off] : 0;
        __syncthreads();
        s[t] += v;
        __syncthreads();
    }
    int prefix = (t == 0) ? 0 : s[t - 1];
    acc = prefix;
    for (int i = 0; i < CH; i++) {
        int idx = base + i;
        if (idx < NV) { g_rowptr[idx] = acc; acc += g_cnt[idx]; }
        else if (idx == NV) { g_rowptr[NV] = acc; }
    }
}

__global__ void k_fill(const int* __restrict__ ei) {
    int i = blockIdx.x * blockDim.x + threadIdx.x;
    int stride = gridDim.x * blockDim.x;
    for (int e = i; e < NE; e += stride) {
        int s = ei[e];
        int d = ei[NE + e];
        int pos = g_rowptr[d] + atomicAdd(&g_cur[d], 1);
        g_srcsorted[pos] = s;
    }
}

// ---------------- GEMM: C[M,N] = A[M,K] @ B[K,N] (+bias) --------------------
__global__ void k_gemm(const float* __restrict__ A, const float* __restrict__ B,
                       const float* __restrict__ bias, float* __restrict__ Cc,
                       int M, int K, int Nn) {
    __shared__ float As[16][65];
    __shared__ float Bs[16][65];
    int tid = threadIdx.x;
    int tx = tid & 15, ty = tid >> 4;
    int row0 = blockIdx.y * 64, col0 = blockIdx.x * 64;
    float acc[4][4] = {};
    for (int k0 = 0; k0 < K; k0 += 16) {
        {   // A tile 64x16, store transposed
            int r = tid >> 2;
            int c4 = (tid & 3) * 4;
            int gr = row0 + r;
            float4 v = make_float4(0.f, 0.f, 0.f, 0.f);
            if (gr < M) v = *reinterpret_cast<const float4*>(A + (size_t)gr * K + k0 + c4);
            As[c4 + 0][r] = v.x; As[c4 + 1][r] = v.y; As[c4 + 2][r] = v.z; As[c4 + 3][r] = v.w;
        }
        {   // B tile 16x64
            int r = tid >> 4;
            int c4 = (tid & 15) * 4;
            float4 v = *reinterpret_cast<const float4*>(B + (size_t)(k0 + r) * Nn + col0 + c4);
            Bs[r][c4 + 0] = v.x; Bs[r][c4 + 1] = v.y; Bs[r][c4 + 2] = v.z; Bs[r][c4 + 3] = v.w;
        }
        __syncthreads();
#pragma unroll
        for (int kk = 0; kk < 16; kk++) {
            float a[4], b[4];
#pragma unroll
            for (int i = 0; i < 4; i++) a[i] = As[kk][ty * 4 + i];
#pragma unroll
            for (int j = 0; j < 4; j++) b[j] = Bs[kk][tx * 4 + j];
#pragma unroll
            for (int i = 0; i < 4; i++)
#pragma unroll
                for (int j = 0; j < 4; j++)
                    acc[i][j] = fmaf(a[i], b[j], acc[i][j]);
        }
        __syncthreads();
    }
#pragma unroll
    for (int i = 0; i < 4; i++) {
        int gr = row0 + ty * 4 + i;
        if (gr >= M) continue;
#pragma unroll
        for (int j = 0; j < 4; j++) {
            int gc = col0 + tx * 4 + j;
            float v = acc[i][j];
            if (bias) v += bias[gc];
            Cc[(size_t)gr * Nn + gc] = v;
        }
    }
}

// ---------------- attention logits per node ---------------------------------
__global__ void k_alpha(const float* __restrict__ aw_s, const float* __restrict__ aw_d) {
    int warp = (blockIdx.x * blockDim.x + threadIdx.x) >> 5;
    int lane = threadIdx.x & 31;
    if (warp >= NV) return;
    const float* hp = g_h + (size_t)warp * C2;
    float s0 = 0.f, s1 = 0.f, d0 = 0.f, d1 = 0.f;
#pragma unroll
    for (int r = 0; r < 4; r++) {
        int o = lane + r * 32;
        float h0 = hp[o], h1 = hp[HID + o];
        s0 = fmaf(h0, aw_s[o], s0);
        s1 = fmaf(h1, aw_s[HID + o], s1);
        d0 = fmaf(h0, aw_d[o], d0);
        d1 = fmaf(h1, aw_d[HID + o], d1);
    }
#pragma unroll
    for (int off = 16; off; off >>= 1) {
        s0 += __shfl_xor_sync(0xffffffffu, s0, off);
        s1 += __shfl_xor_sync(0xffffffffu, s1, off);
        d0 += __shfl_xor_sync(0xffffffffu, d0, off);
        d1 += __shfl_xor_sync(0xffffffffu, d1, off);
    }
    if (lane == 0) {
        g_as[2 * warp] = s0; g_as[2 * warp + 1] = s1;
        g_ad[2 * warp] = d0; g_ad[2 * warp + 1] = d1;
    }
}

// ---------------- virtual-node softmax chain --------------------------------
__global__ void k_vpart() {                 // grid VPART_BLOCKS x 256
    __shared__ float s0[256], s1[256];
    int t = threadIdx.x;
    float adv0 = g_ad[2 * NN], adv1 = g_ad[2 * NN + 1];
    float m0 = -3.4e38f, m1 = -3.4e38f;
    for (int j = blockIdx.x * 256 + t; j < NV; j += VPART_BLOCKS * 256) {
        m0 = fmaxf(m0, lrelu(g_as[2 * j] + adv0));
        m1 = fmaxf(m1, lrelu(g_as[2 * j + 1] + adv1));
    }
    s0[t] = m0; s1[t] = m1;
    __syncthreads();
    for (int off = 128; off; off >>= 1) {
        if (t < off) { s0[t] = fmaxf(s0[t], s0[t + off]); s1[t] = fmaxf(s1[t], s1[t + off]); }
        __syncthreads();
    }
    if (t == 0) { g_vmaxpart[2 * blockIdx.x] = s0[0]; g_vmaxpart[2 * blockIdx.x + 1] = s1[0]; }
}

__global__ void k_vmid() {                  // 1 block x 256
    __shared__ float s0[256], s1[256];
    int t = threadIdx.x;
    float a = -3.4e38f, b = -3.4e38f;
    if (t < VPART_BLOCKS) { a = g_vmaxpart[2 * t]; b = g_vmaxpart[2 * t + 1]; }
    s0[t] = a; s1[t] = b;
    __syncthreads();
    for (int off = 128; off; off >>= 1) {
        if (t < off) { s0[t] = fmaxf(s0[t], s0[t + off]); s1[t] = fmaxf(s1[t], s1[t + off]); }
        __syncthreads();
    }
    if (t == 0) { g_vred[0] = s0[0]; g_vred[1] = s1[0]; g_vden[0] = 0.f; g_vden[1] = 0.f; }
    if (t < C2) g_vS[t] = 0.f;
}

__global__ void k_vacc() {                  // 256 blocks x 256 (warp per row, strided)
    int gw = (blockIdx.x * blockDim.x + threadIdx.x) >> 5;
    int lane = threadIdx.x & 31;
    int nw = (gridDim.x * blockDim.x) >> 5;
    float m0 = g_vred[0], m1 = g_vred[1];
    float adv0 = g_ad[2 * NN], adv1 = g_ad[2 * NN + 1];
    float acc[8] = {};
    float den0 = 0.f, den1 = 0.f;
    for (int j = gw; j < NV; j += nw) {
        float e0 = expf(lrelu(g_as[2 * j] + adv0) - m0);
        float e1 = expf(lrelu(g_as[2 * j + 1] + adv1) - m1);
        den0 += e0; den1 += e1;
        const float* hp = g_h + (size_t)j * C2;
#pragma unroll
        for (int r = 0; r < 8; r++) {
            float c = (r < 4) ? e0 : e1;
            acc[r] = fmaf(c, hp[lane + r * 32], acc[r]);
        }
    }
#pragma unroll
    for (int r = 0; r < 8; r++) atomicAdd(&g_vS[lane + r * 32], acc[r]);
    if (lane == 0) { atomicAdd(&g_vden[0], den0); atomicAdd(&g_vden[1], den1); }
}

__global__ void k_vnodefinal(const float* __restrict__ b, const float* __restrict__ gam,
                             const float* __restrict__ bet, float* __restrict__ xn) {
    int o = threadIdx.x;                   // 128 threads
    float den0 = g_vden[0] + 1e-16f, den1 = g_vden[1] + 1e-16f;
    float v = 0.5f * (g_vS[o] / den0 + g_vS[HID + o] / den1) + b[o];
    __shared__ float ssum[4], ssq[4];
    float ls = v, lq = v * v;
#pragma unroll
    for (int off = 16; off; off >>= 1) {
        ls += __shfl_xor_sync(0xffffffffu, ls, off);
        lq += __shfl_xor_sync(0xffffffffu, lq, off);
    }
    int wid = o >> 5, lane = o & 31;
    if (lane == 0) { ssum[wid] = ls; ssq[wid] = lq; }
    __syncthreads();
    float ts = ssum[0] + ssum[1] + ssum[2] + ssum[3];
    float tq = ssq[0] + ssq[1] + ssq[2] + ssq[3];
    float mu = ts * (1.0f / HID);
    float var = tq * (1.0f / HID) - mu * mu;
    float y = (v - mu) * rsqrtf(var + 1e-5f) * gam[o] + bet[o];
    y = 0.5f * y * (1.f + erff(y * 0.70710678118654752f));
    xn[NN * HID + o] = y;
}

// ---------------- per-node aggregation + LN + GELU (warp per node) ----------
__global__ void k_nodeagg(const float* __restrict__ b, const float* __restrict__ gam,
                          const float* __restrict__ bet, float* __restrict__ xn) {
    int i = (blockIdx.x * blockDim.x + threadIdx.x) >> 5;
    int lane = threadIdx.x & 31;
    if (i >= NN) return;
    float ad0 = g_ad[2 * i], ad1 = g_ad[2 * i + 1];
    float z_self0 = lrelu(g_as[2 * i] + ad0);
    float z_self1 = lrelu(g_as[2 * i + 1] + ad1);
    float z_v0 = lrelu(g_as[2 * NN] + ad0);
    float z_v1 = lrelu(g_as[2 * NN + 1] + ad1);
    int beg = g_rowptr[i], end = g_rowptr[i + 1];

    // pass 1: max over incoming logits (orig edges + self loop + vnode edge)
    float m0 = fmaxf(z_self0, z_v0), m1 = fmaxf(z_self1, z_v1);
    for (int e = beg + lane; e < end; e += 32) {
        int s = g_srcsorted[e];
        m0 = fmaxf(m0, lrelu(g_as[2 * s] + ad0));
        m1 = fmaxf(m1, lrelu(g_as[2 * s + 1] + ad1));
    }
#pragma unroll
    for (int off = 16; off; off >>= 1) {
        m0 = fmaxf(m0, __shfl_xor_sync(0xffffffffu, m0, off));
        m1 = fmaxf(m1, __shfl_xor_sync(0xffffffffu, m1, off));
    }

    // pass 2: weighted accumulate (serial over edges, warp-parallel over features)
    float acc[8] = {};
    float den0, den1;
    {
        float c0 = expf(z_self0 - m0), c1 = expf(z_self1 - m1);
        den0 = c0; den1 = c1;
        const float* hp = g_h + (size_t)i * C2;
#pragma unroll
        for (int r = 0; r < 8; r++) acc[r] = fmaf((r < 4) ? c0 : c1, hp[lane + r * 32], acc[r]);
        c0 = expf(z_v0 - m0); c1 = expf(z_v1 - m1);
        den0 += c0; den1 += c1;
        const float* hv = g_h + (size_t)NN * C2;
#pragma unroll
        for (int r = 0; r < 8; r++) acc[r] = fmaf((r < 4) ? c0 : c1, hv[lane + r * 32], acc[r]);
    }
    for (int e = beg; e < end; e++) {
        int s = g_srcsorted[e];
        float c0 = expf(lrelu(g_as[2 * s] + ad0) - m0);
        float c1 = expf(lrelu(g_as[2 * s + 1] + ad1) - m1);
        den0 += c0; den1 += c1;
        const float* hp = g_h + (size_t)s * C2;
#pragma unroll
        for (int r = 0; r < 8; r++) acc[r] = fmaf((r < 4) ? c0 : c1, hp[lane + r * 32], acc[r]);
    }

    float inv0 = 0.5f / (den0 + 1e-16f);
    float inv1 = 0.5f / (den1 + 1e-16f);
    float v[4], lsum = 0.f, lsq = 0.f;
#pragma unroll
    for (int r = 0; r < 4; r++) {
        int o = lane + r * 32;
        v[r] = acc[r] * inv0 + acc[4 + r] * inv1 + b[o];
        lsum += v[r];
        lsq = fmaf(v[r], v[r], lsq);
    }
#pragma unroll
    for (int off = 16; off; off >>= 1) {
        lsum += __shfl_xor_sync(0xffffffffu, lsum, off);
        lsq += __shfl_xor_sync(0xffffffffu, lsq, off);
    }
    float mu = lsum * (1.0f / HID);
    float var = lsq * (1.0f / HID) - mu * mu;
    float rstd = rsqrtf(var + 1e-5f);
#pragma unroll
    for (int r = 0; r < 4; r++) {
        int o = lane + r * 32;
        float y = (v[r] - mu) * rstd * gam[o] + bet[o];
        y = 0.5f * y * (1.f + erff(y * 0.70710678118654752f));
        xn[i * HID + o] = y;
    }
}

// ---------------- host orchestration ----------------------------------------
extern "C" void kernel_launch(void* const* d_in, const int* in_sizes, int n_in,
                              void* d_out, int out_size) {
    const float* X  = (const float*)d_in[0];
    const int*   ei = (const int*)d_in[1];
    // d_in[2] = edge_weight (unused by reference)
    const float* W[3]    = { (const float*)d_in[3],  (const float*)d_in[9],  (const float*)d_in[15] };
    const float* a_s[3]  = { (const float*)d_in[4],  (const float*)d_in[10], (const float*)d_in[16] };
    const float* a_d[3]  = { (const float*)d_in[5],  (const float*)d_in[11], (const float*)d_in[17] };
    const float* bb[3]   = { (const float*)d_in[6],  (const float*)d_in[12], (const float*)d_in[18] };
    const float* gg[3]   = { (const float*)d_in[7],  (const float*)d_in[13], (const float*)d_in[19] };
    const float* be[3]   = { (const float*)d_in[8],  (const float*)d_in[14], (const float*)d_in[20] };
    const float* Wout = (const float*)d_in[21];
    const float* bout = (const float*)d_in[22];

    float *p_x0, *p_xa, *p_xb, *p_h;
    cudaGetSymbolAddress((void**)&p_x0, g_x0);
    cudaGetSymbolAddress((void**)&p_xa, g_xa);
    cudaGetSymbolAddress((void**)&p_xb, g_xb);
    cudaGetSymbolAddress((void**)&p_h,  g_h);

    k_zero<<<200, 256>>>();
    k_copyX<<<4096, 256>>>(X);
    k_colsum<<<256, 256>>>(X);
    k_vrow<<<1, IND>>>();
    k_hist<<<1024, 256>>>(ei);
    k_scan<<<1, 1024>>>();
    k_fill<<<1024, 256>>>(ei);

    for (int l = 0; l < 3; l++) {
        const float* A = (l == 0) ? p_x0 : ((l == 1) ? p_xa : p_xb);
        int K = (l == 0) ? IND : HID;
        float* xn = (l == 0) ? p_xa : ((l == 1) ? p_xb : p_xa);

        dim3 grid(C2 / 64, (NV + 63) / 64);
        k_gemm<<<grid, 256>>>(A, W[l], nullptr, p_h, NV, K, C2);
        k_alpha<<<(NV * 32 + 255) / 256, 256>>>(a_s[l], a_d[l]);
        k_vpart<<<VPART_BLOCKS, 256>>>();
        k_vmid<<<1, 256>>>();
        k_vacc<<<256, 256>>>();
        k_nodeagg<<<(NN * 32 + 255) / 256, 256>>>(bb[l], gg[l], be[l], xn);
        k_vnodefinal<<<1, HID>>>(bb[l], gg[l], be[l], xn);
    }

    // final projection: out[NN, OD] = xa[NN, HID] @ Wout + bout
    dim3 grid_out(1, (NN + 63) / 64);
    k_gemm<<<grid_out, 256>>>(p_xa, Wout, bout, (float*)d_out, NN, HID, OD);
}

// round 3
// speedup vs baseline: 1.3471x; 1.3471x over previous
#include <cuda_runtime.h>
#include <cuda_bf16.h>
#include <math.h>
#include <stdint.h>

#define NN   50000      // real nodes
#define NV   50001      // nodes + virtual node
#define NPAD 50048      // 391 * 128, padded M for MMA tiles
#define NE   400000     // original edges
#define IND  256        // input dim
#define HID  128        // hidden dim
#define NH   2          // heads
#define C2   256        // NH*HID
#define OD   64         // output dim
#define VPART_BLOCKS 112

// ---------------- static device scratch -------------------------------------
__device__ __nv_bfloat16 g_Ahi[(size_t)NPAD * IND];   // GEMM A input, hi part
__device__ __nv_bfloat16 g_Alo[(size_t)NPAD * IND];   // GEMM A input, lo part
__device__ __nv_bfloat16 g_Bthi[C2 * IND];            // B^T (N-major, k-contig) hi
__device__ __nv_bfloat16 g_Btlo[C2 * IND];            // B^T lo
__device__ float g_h[(size_t)NV * C2];                // transformed features
__device__ float g_as[NV * NH];
__device__ float g_ad[NV * NH];
__device__ int   g_cnt[NV];
__device__ int   g_cur[NV];
__device__ int   g_rowptr[NV + 1];
__device__ int   g_srcsorted[NE];
__device__ float g_colsum[IND];
__device__ float g_vmaxpart[VPART_BLOCKS * NH];
__device__ float g_vred[NH];
__device__ float g_vS[C2];
__device__ float g_vden[NH];

__device__ __forceinline__ float lrelu(float x) { return x > 0.f ? x : 0.2f * x; }

__device__ __forceinline__ uint32_t smem_to_u32(const void* p) {
    uint32_t a;
    asm("{ .reg .u64 t; cvta.to.shared.u64 t, %1; cvt.u32.u64 %0, t; }" : "=r"(a) : "l"(p));
    return a;
}

#define SW128(off) ((off) ^ (((off) >> 3) & 0x70))

#define LDSM_X4(r0, r1, r2, r3, addr) \
    asm volatile("ldmatrix.sync.aligned.m8n8.x4.shared.b16 {%0,%1,%2,%3}, [%4];" \
        : "=r"(r0), "=r"(r1), "=r"(r2), "=r"(r3) : "r"(addr))

__device__ __forceinline__ void mma16816(float* c, const uint32_t* a, uint32_t b0, uint32_t b1) {
    asm volatile("mma.sync.aligned.m16n8k16.row.col.f32.bf16.bf16.f32 "
        "{%0,%1,%2,%3}, {%4,%5,%6,%7}, {%8,%9}, {%0,%1,%2,%3};"
        : "+f"(c[0]), "+f"(c[1]), "+f"(c[2]), "+f"(c[3])
        : "r"(a[0]), "r"(a[1]), "r"(a[2]), "r"(a[3]), "r"(b0), "r"(b1));
}

// ---------------- misc init -------------------------------------------------
__global__ void k_zero() {
    int i = blockIdx.x * blockDim.x + threadIdx.x;
    int stride = gridDim.x * blockDim.x;
    for (int j = i; j < NV; j += stride) { g_cnt[j] = 0; g_cur[j] = 0; }
    if (i < IND) g_colsum[i] = 0.f;
}

__global__ void k_convX(const float* __restrict__ X) {
    int i = blockIdx.x * blockDim.x + threadIdx.x;
    int stride = gridDim.x * blockDim.x;
    const int total = NN * IND;
    for (int j = i; j < total; j += stride) {
        float v = X[j];
        __nv_bfloat16 hi = __float2bfloat16(v);
        g_Ahi[j] = hi;
        g_Alo[j] = __float2bfloat16(v - __bfloat162float(hi));
    }
}

__global__ void k_colsum(const float* __restrict__ X) {
    int c = threadIdx.x;
    float s = 0.f;
    for (int r = blockIdx.x; r < NN; r += gridDim.x)
        s += X[r * IND + c];
    atomicAdd(&g_colsum[c], s);
}

__global__ void k_vrowconv() {
    int c = threadIdx.x;
    float v = g_colsum[c] * (1.0f / NN);
    __nv_bfloat16 hi = __float2bfloat16(v);
    g_Ahi[(size_t)NN * IND + c] = hi;
    g_Alo[(size_t)NN * IND + c] = __float2bfloat16(v - __bfloat162float(hi));
}

// Bt[n*K + k] = W[k*Ncols + n], split hi/lo
__global__ void k_convW(const float* __restrict__ W, int K, int Ncols) {
    int i = blockIdx.x * blockDim.x + threadIdx.x;
    int total = K * Ncols;
    if (i >= total) return;
    int n = i / K, k = i % K;
    float v = W[k * Ncols + n];
    __nv_bfloat16 hi = __float2bfloat16(v);
    g_Bthi[n * K + k] = hi;
    g_Btlo[n * K + k] = __float2bfloat16(v - __bfloat162float(hi));
}

// ---------------- CSR build -------------------------------------------------
__global__ void k_hist(const int* __restrict__ ei) {
    int i = blockIdx.x * blockDim.x + threadIdx.x;
    int stride = gridDim.x * blockDim.x;
    for (int e = i; e < NE; e += stride)
        atomicAdd(&g_cnt[ei[NE + e]], 1);
}

__global__ void k_scan() {
    __shared__ int s[1024];
    int t = threadIdx.x;
    const int CH = (NV + 1023) / 1024;
    int base = t * CH;
    int acc = 0;
    for (int i = 0; i < CH; i++) { int idx = base + i; if (idx < NV) acc += g_cnt[idx]; }
    s[t] = acc;
    __syncthreads();
    for (int off = 1; off < 1024; off <<= 1) {
        int v = (t >= off) ? s[t - off] : 0;
        __syncthreads();
        s[t] += v;
        __syncthreads();
    }
    int prefix = (t == 0) ? 0 : s[t - 1];
    acc = prefix;
    for (int i = 0; i < CH; i++) {
        int idx = base + i;
        if (idx < NV) { g_rowptr[idx] = acc; acc += g_cnt[idx]; }
        else if (idx == NV) { g_rowptr[NV] = acc; }
    }
}

__global__ void k_fill(const int* __restrict__ ei) {
    int i = blockIdx.x * blockDim.x + threadIdx.x;
    int stride = gridDim.x * blockDim.x;
    for (int e = i; e < NE; e += stride) {
        int s = ei[e];
        int d = ei[NE + e];
        int pos = g_rowptr[d] + atomicAdd(&g_cur[d], 1);
        g_srcsorted[pos] = s;
    }
}

// ---------------- HMMA (mma.sync) GEMM ---------------------------------------
// C[M, NTOT] = A[M, KTOT] @ Bt^T. A row-major (k-contig), Bt [NTOT][KTOT] (k-contig).
// hi/lo bf16 3-product split accumulated into fp32 registers.
// Block tile 128 x NTB (NTB = min(NTOT,128)), 8 warps = 4(M) x 2(N), warp 32 x NTB/2.
template<int KTOT, int NTOT, bool BIAS>
__global__ void __launch_bounds__(256, 1) k_hgemm(
    const __nv_bfloat16* __restrict__ Ahi, const __nv_bfloat16* __restrict__ Alo,
    const __nv_bfloat16* __restrict__ Bhi, const __nv_bfloat16* __restrict__ Blo,
    float* __restrict__ Cout, int M, const float* __restrict__ bias)
{
    constexpr int NTB = (NTOT < 128) ? NTOT : 128;
    constexpr int NCH = KTOT / 64;       // k-chunks of 64
    constexpr int NTW = (NTB / 2) / 8;   // n8-tiles per warp (8 or 4)
    constexpr int NJP = NTW / 2;         // ldmatrix.x4 pairs
    constexpr int OFF_ALO = 16384;
    constexpr int OFF_BHI = 32768;
    constexpr int OFF_BLO = 32768 + NTB * 128;

    extern __shared__ char smem[];
    uint32_t sb = smem_to_u32(smem);
    int tid = threadIdx.x, wid = tid >> 5, lane = tid & 31;
    int wm = wid >> 1, wn = wid & 1;
    int row0 = blockIdx.x * 128;
    int col0 = blockIdx.y * NTB;

    float acc[2][NTW][4];
#pragma unroll
    for (int mt = 0; mt < 2; mt++)
#pragma unroll
        for (int nt = 0; nt < NTW; nt++)
#pragma unroll
            for (int j = 0; j < 4; j++) acc[mt][nt][j] = 0.f;

    // per-lane ldmatrix address precompute
    uint32_t sw = (lane & 7) * 16;
    int lmrow = ((lane >> 3) & 1) * 8 + (lane & 7);
    uint32_t lakoff = ((lane >> 4) & 1) * 16;
    int bnrow = ((lane >> 4) & 1) * 8 + (lane & 7);
    uint32_t bkoff = ((lane >> 3) & 1) * 16;
    uint32_t aoff[2];
#pragma unroll
    for (int mt = 0; mt < 2; mt++)
        aoff[mt] = sb + (uint32_t)(wm * 32 + mt * 16 + lmrow) * 128;
    uint32_t boff[NJP];
#pragma unroll
    for (int jp = 0; jp < NJP; jp++)
        boff[jp] = sb + OFF_BHI + (uint32_t)(wn * (NTB / 2) + jp * 16 + bnrow) * 128;

    for (int ch = 0; ch < NCH; ch++) {
        // cooperative load A tiles: 128 rows x 64 bf16 (SW128)
        for (int u = tid; u < 128 * 8; u += 256) {
            int r = u >> 3, c8 = u & 7;
            size_t gidx = (size_t)(row0 + r) * KTOT + ch * 64 + c8 * 8;
            uint32_t soff = SW128((uint32_t)(r * 128 + c8 * 16));
            *(uint4*)(smem + soff) = *(const uint4*)(Ahi + gidx);
            *(uint4*)(smem + OFF_ALO + soff) = *(const uint4*)(Alo + gidx);
        }
        // B tiles: NTB rows x 64 bf16
        for (int u = tid; u < NTB * 8; u += 256) {
            int r = u >> 3, c8 = u & 7;
            size_t gidx = (size_t)(col0 + r) * KTOT + ch * 64 + c8 * 8;
            uint32_t soff = SW128((uint32_t)(r * 128 + c8 * 16));
            *(uint4*)(smem + OFF_BHI + soff) = *(const uint4*)(Bhi + gidx);
            *(uint4*)(smem + OFF_BLO + soff) = *(const uint4*)(Blo + gidx);
        }
        __syncthreads();

#pragma unroll
        for (int ks = 0; ks < 4; ks++) {
            uint32_t kba = (uint32_t)(ks * 32 + lakoff) ^ sw;
            uint32_t ah[2][4], al[2][4];
#pragma unroll
            for (int mt = 0; mt < 2; mt++) {
                LDSM_X4(ah[mt][0], ah[mt][1], ah[mt][2], ah[mt][3], aoff[mt] + kba);
                LDSM_X4(al[mt][0], al[mt][1], al[mt][2], al[mt][3], aoff[mt] + OFF_ALO + kba);
            }
            uint32_t kbb = (uint32_t)(ks * 32 + bkoff) ^ sw;
#pragma unroll
            for (int jp = 0; jp < NJP; jp++) {
                uint32_t bh0, bh1, bh2, bh3, bl0, bl1, bl2, bl3;
                LDSM_X4(bh0, bh1, bh2, bh3, boff[jp] + kbb);
                LDSM_X4(bl0, bl1, bl2, bl3, boff[jp] + (NTB * 128) + kbb);
#pragma unroll
                for (int mt = 0; mt < 2; mt++) {
                    mma16816(acc[mt][2 * jp], ah[mt], bh0, bh1);
                    mma16816(acc[mt][2 * jp], al[mt], bh0, bh1);
                    mma16816(acc[mt][2 * jp], ah[mt], bl0, bl1);
                    mma16816(acc[mt][2 * jp + 1], ah[mt], bh2, bh3);
                    mma16816(acc[mt][2 * jp + 1], al[mt], bh2, bh3);
                    mma16816(acc[mt][2 * jp + 1], ah[mt], bl2, bl3);
                }
            }
        }
        __syncthreads();
    }

    // epilogue
    int g = lane >> 2, t = lane & 3;
#pragma unroll
    for (int mt = 0; mt < 2; mt++) {
#pragma unroll
        for (int nt = 0; nt < NTW; nt++) {
            int gr = row0 + wm * 32 + mt * 16 + g;
            int gc = col0 + wn * (NTB / 2) + nt * 8 + t * 2;
            float b0 = 0.f, b1 = 0.f;
            if (BIAS) { b0 = bias[gc]; b1 = bias[gc + 1]; }
            if (gr < M) {
                float2 v = make_float2(acc[mt][nt][0] + b0, acc[mt][nt][1] + b1);
                *(float2*)&Cout[(size_t)gr * NTOT + gc] = v;
            }
            if (gr + 8 < M) {
                float2 v = make_float2(acc[mt][nt][2] + b0, acc[mt][nt][3] + b1);
                *(float2*)&Cout[(size_t)(gr + 8) * NTOT + gc] = v;
            }
        }
    }
}

// ---------------- attention logits per node ---------------------------------
__global__ void k_alpha(const float* __restrict__ aw_s, const float* __restrict__ aw_d) {
    int warp = (blockIdx.x * blockDim.x + threadIdx.x) >> 5;
    int lane = threadIdx.x & 31;
    if (warp >= NV) return;
    const float* hp = g_h + (size_t)warp * C2;
    float s0 = 0.f, s1 = 0.f, d0 = 0.f, d1 = 0.f;
#pragma unroll
    for (int r = 0; r < 4; r++) {
        int o = lane + r * 32;
        float h0 = hp[o], h1 = hp[HID + o];
        s0 = fmaf(h0, aw_s[o], s0);
        s1 = fmaf(h1, aw_s[HID + o], s1);
        d0 = fmaf(h0, aw_d[o], d0);
        d1 = fmaf(h1, aw_d[HID + o], d1);
    }
#pragma unroll
    for (int off = 16; off; off >>= 1) {
        s0 += __shfl_xor_sync(0xffffffffu, s0, off);
        s1 += __shfl_xor_sync(0xffffffffu, s1, off);
        d0 += __shfl_xor_sync(0xffffffffu, d0, off);
        d1 += __shfl_xor_sync(0xffffffffu, d1, off);
    }
    if (lane == 0) {
        g_as[2 * warp] = s0; g_as[2 * warp + 1] = s1;
        g_ad[2 * warp] = d0; g_ad[2 * warp + 1] = d1;
    }
}

// ---------------- virtual-node softmax chain --------------------------------
__global__ void k_vpart() {
    __shared__ float s0[256], s1[256];
    int t = threadIdx.x;
    float adv0 = g_ad[2 * NN], adv1 = g_ad[2 * NN + 1];
    float m0 = -3.4e38f, m1 = -3.4e38f;
    for (int j = blockIdx.x * 256 + t; j < NV; j += VPART_BLOCKS * 256) {
        m0 = fmaxf(m0, lrelu(g_as[2 * j] + adv0));
        m1 = fmaxf(m1, lrelu(g_as[2 * j + 1] + adv1));
    }
    s0[t] = m0; s1[t] = m1;
    __syncthreads();
    for (int off = 128; off; off >>= 1) {
        if (t < off) { s0[t] = fmaxf(s0[t], s0[t + off]); s1[t] = fmaxf(s1[t], s1[t + off]); }
        __syncthreads();
    }
    if (t == 0) { g_vmaxpart[2 * blockIdx.x] = s0[0]; g_vmaxpart[2 * blockIdx.x + 1] = s1[0]; }
}

__global__ void k_vmid() {
    __shared__ float s0[256], s1[256];
    int t = threadIdx.x;
    float a = -3.4e38f, b = -3.4e38f;
    if (t < VPART_BLOCKS) { a = g_vmaxpart[2 * t]; b = g_vmaxpart[2 * t + 1]; }
    s0[t] = a; s1[t] = b;
    __syncthreads();
    for (int off = 128; off; off >>= 1) {
        if (t < off) { s0[t] = fmaxf(s0[t], s0[t + off]); s1[t] = fmaxf(s1[t], s1[t + off]); }
        __syncthreads();
    }
    if (t == 0) { g_vred[0] = s0[0]; g_vred[1] = s1[0]; g_vden[0] = 0.f; g_vden[1] = 0.f; }
    if (t < C2) g_vS[t] = 0.f;
}

__global__ void k_vacc() {
    int gw = (blockIdx.x * blockDim.x + threadIdx.x) >> 5;
    int lane = threadIdx.x & 31;
    int nw = (gridDim.x * blockDim.x) >> 5;
    float m0 = g_vred[0], m1 = g_vred[1];
    float adv0 = g_ad[2 * NN], adv1 = g_ad[2 * NN + 1];
    float acc[8] = {};
    float den0 = 0.f, den1 = 0.f;
    for (int j = gw; j < NV; j += nw) {
        float e0 = expf(lrelu(g_as[2 * j] + adv0) - m0);
        float e1 = expf(lrelu(g_as[2 * j + 1] + adv1) - m1);
        den0 += e0; den1 += e1;
        const float* hp = g_h + (size_t)j * C2;
#pragma unroll
        for (int r = 0; r < 8; r++) {
            float c = (r < 4) ? e0 : e1;
            acc[r] = fmaf(c, hp[lane + r * 32], acc[r]);
        }
    }
#pragma unroll
    for (int r = 0; r < 8; r++) atomicAdd(&g_vS[lane + r * 32], acc[r]);
    if (lane == 0) { atomicAdd(&g_vden[0], den0); atomicAdd(&g_vden[1], den1); }
}

__global__ void k_vnodefinal(const float* __restrict__ b, const float* __restrict__ gam,
                             const float* __restrict__ bet) {
    int o = threadIdx.x;                   // 128 threads
    float den0 = g_vden[0] + 1e-16f, den1 = g_vden[1] + 1e-16f;
    float v = 0.5f * (g_vS[o] / den0 + g_vS[HID + o] / den1) + b[o];
    __shared__ float ssum[4], ssq[4];
    float ls = v, lq = v * v;
#pragma unroll
    for (int off = 16; off; off >>= 1) {
        ls += __shfl_xor_sync(0xffffffffu, ls, off);
        lq += __shfl_xor_sync(0xffffffffu, lq, off);
    }
    int wid = o >> 5, lane = o & 31;
    if (lane == 0) { ssum[wid] = ls; ssq[wid] = lq; }
    __syncthreads();
    float ts = ssum[0] + ssum[1] + ssum[2] + ssum[3];
    float tq = ssq[0] + ssq[1] + ssq[2] + ssq[3];
    float mu = ts * (1.0f / HID);
    float var = tq * (1.0f / HID) - mu * mu;
    float y = (v - mu) * rsqrtf(var + 1e-5f) * gam[o] + bet[o];
    y = 0.5f * y * (1.f + erff(y * 0.70710678118654752f));
    __nv_bfloat16 hi = __float2bfloat16(y);
    g_Ahi[(size_t)NN * HID + o] = hi;
    g_Alo[(size_t)NN * HID + o] = __float2bfloat16(y - __bfloat162float(hi));
}

// ---------------- per-node aggregation + LN + GELU (warp per node) ----------
__global__ void k_nodeagg(const float* __restrict__ b, const float* __restrict__ gam,
                          const float* __restrict__ bet) {
    int i = (blockIdx.x * blockDim.x + threadIdx.x) >> 5;
    int lane = threadIdx.x & 31;
    if (i >= NN) return;
    float ad0 = g_ad[2 * i], ad1 = g_ad[2 * i + 1];
    float z_self0 = lrelu(g_as[2 * i] + ad0);
    float z_self1 = lrelu(g_as[2 * i + 1] + ad1);
    float z_v0 = lrelu(g_as[2 * NN] + ad0);
    float z_v1 = lrelu(g_as[2 * NN + 1] + ad1);
    int beg = g_rowptr[i], end = g_rowptr[i + 1];

    float m0 = fmaxf(z_self0, z_v0), m1 = fmaxf(z_self1, z_v1);
    for (int e = beg + lane; e < end; e += 32) {
        int s = g_srcsorted[e];
        m0 = fmaxf(m0, lrelu(g_as[2 * s] + ad0));
        m1 = fmaxf(m1, lrelu(g_as[2 * s + 1] + ad1));
    }
#pragma unroll
    for (int off = 16; off; off >>= 1) {
        m0 = fmaxf(m0, __shfl_xor_sync(0xffffffffu, m0, off));
        m1 = fmaxf(m1, __shfl_xor_sync(0xffffffffu, m1, off));
    }

    float acc[8] = {};
    float den0, den1;
    {
        float c0 = expf(z_self0 - m0), c1 = expf(z_self1 - m1);
        den0 = c0; den1 = c1;
        const float* hp = g_h + (size_t)i * C2;
#pragma unroll
        for (int r = 0; r < 8; r++) acc[r] = fmaf((r < 4) ? c0 : c1, hp[lane + r * 32], acc[r]);
        c0 = expf(z_v0 - m0); c1 = expf(z_v1 - m1);
        den0 += c0; den1 += c1;
        const float* hv = g_h + (size_t)NN * C2;
#pragma unroll
        for (int r = 0; r < 8; r++) acc[r] = fmaf((r < 4) ? c0 : c1, hv[lane + r * 32], acc[r]);
    }
    for (int e = beg; e < end; e++) {
        int s = g_srcsorted[e];
        float c0 = expf(lrelu(g_as[2 * s] + ad0) - m0);
        float c1 = expf(lrelu(g_as[2 * s + 1] + ad1) - m1);
        den0 += c0; den1 += c1;
        const float* hp = g_h + (size_t)s * C2;
#pragma unroll
        for (int r = 0; r < 8; r++) acc[r] = fmaf((r < 4) ? c0 : c1, hp[lane + r * 32], acc[r]);
    }

    float inv0 = 0.5f / (den0 + 1e-16f);
    float inv1 = 0.5f / (den1 + 1e-16f);
    float v[4], lsum = 0.f, lsq = 0.f;
#pragma unroll
    for (int r = 0; r < 4; r++) {
        int o = lane + r * 32;
        v[r] = acc[r] * inv0 + acc[4 + r] * inv1 + b[o];
        lsum += v[r];
        lsq = fmaf(v[r], v[r], lsq);
    }
#pragma unroll
    for (int off = 16; off; off >>= 1) {
        lsum += __shfl_xor_sync(0xffffffffu, lsum, off);
        lsq += __shfl_xor_sync(0xffffffffu, lsq, off);
    }
    float mu = lsum * (1.0f / HID);
    float var = lsq * (1.0f / HID) - mu * mu;
    float rstd = rsqrtf(var + 1e-5f);
#pragma unroll
    for (int r = 0; r < 4; r++) {
        int o = lane + r * 32;
        float y = (v[r] - mu) * rstd * gam[o] + bet[o];
        y = 0.5f * y * (1.f + erff(y * 0.70710678118654752f));
        __nv_bfloat16 hi = __float2bfloat16(y);
        g_Ahi[(size_t)i * HID + o] = hi;
        g_Alo[(size_t)i * HID + o] = __float2bfloat16(y - __bfloat162float(hi));
    }
}

// ---------------- host orchestration ----------------------------------------
extern "C" void kernel_launch(void* const* d_in, const int* in_sizes, int n_in,
                              void* d_out, int out_size) {
    const float* X  = (const float*)d_in[0];
    const int*   ei = (const int*)d_in[1];
    const float* W[3]    = { (const float*)d_in[3],  (const float*)d_in[9],  (const float*)d_in[15] };
    const float* a_s[3]  = { (const float*)d_in[4],  (const float*)d_in[10], (const float*)d_in[16] };
    const float* a_d[3]  = { (const float*)d_in[5],  (const float*)d_in[11], (const float*)d_in[17] };
    const float* bb[3]   = { (const float*)d_in[6],  (const float*)d_in[12], (const float*)d_in[18] };
    const float* gg[3]   = { (const float*)d_in[7],  (const float*)d_in[13], (const float*)d_in[19] };
    const float* be[3]   = { (const float*)d_in[8],  (const float*)d_in[14], (const float*)d_in[20] };
    const float* Wout = (const float*)d_in[21];
    const float* bout = (const float*)d_in[22];

    __nv_bfloat16 *pAhi, *pAlo, *pBhi, *pBlo;
    float* p_h;
    cudaGetSymbolAddress((void**)&pAhi, g_Ahi);
    cudaGetSymbolAddress((void**)&pAlo, g_Alo);
    cudaGetSymbolAddress((void**)&pBhi, g_Bthi);
    cudaGetSymbolAddress((void**)&pBlo, g_Btlo);
    cudaGetSymbolAddress((void**)&p_h,  g_h);

    const int SM256 = 32768 + 2 * 128 * 128;   // 65536
    const int SM64  = 32768 + 2 * 64 * 128;    // 49152
    cudaFuncSetAttribute(k_hgemm<256, 256, false>, cudaFuncAttributeMaxDynamicSharedMemorySize, SM256);
    cudaFuncSetAttribute(k_hgemm<128, 256, false>, cudaFuncAttributeMaxDynamicSharedMemorySize, SM256);
    cudaFuncSetAttribute(k_hgemm<128, 64,  true>,  cudaFuncAttributeMaxDynamicSharedMemorySize, SM64);

    k_zero<<<200, 256>>>();
    k_convX<<<8192, 256>>>(X);
    k_colsum<<<256, 256>>>(X);
    k_vrowconv<<<1, IND>>>();
    k_hist<<<1024, 256>>>(ei);
    k_scan<<<1, 1024>>>();
    k_fill<<<1024, 256>>>(ei);

    const int NBLK = NPAD / 128;   // 391

    for (int l = 0; l < 3; l++) {
        int K = (l == 0) ? IND : HID;
        k_convW<<<(K * C2 + 255) / 256, 256>>>(W[l], K, C2);
        dim3 grid(NBLK, 2);
        if (l == 0)
            k_hgemm<256, 256, false><<<grid, 256, SM256>>>(pAhi, pAlo, pBhi, pBlo, p_h, NV, nullptr);
        else
            k_hgemm<128, 256, false><<<grid, 256, SM256>>>(pAhi, pAlo, pBhi, pBlo, p_h, NV, nullptr);
        k_alpha<<<(NV * 32 + 255) / 256, 256>>>(a_s[l], a_d[l]);
        k_vpart<<<VPART_BLOCKS, 256>>>();
        k_vmid<<<1, 256>>>();
        k_vacc<<<256, 256>>>();
        k_nodeagg<<<(NN * 32 + 255) / 256, 256>>>(bb[l], gg[l], be[l]);
        k_vnodefinal<<<1, HID>>>(bb[l], gg[l], be[l]);
    }

    k_convW<<<(HID * OD + 255) / 256, 256>>>(Wout, HID, OD);
    k_hgemm<128, 64, true><<<dim3(NBLK, 1), 256, SM64>>>(pAhi, pAlo, pBhi, pBlo, (float*)d_out, NN, bout);
}

// round 4
// speedup vs baseline: 1.7616x; 1.3077x over previous
#include <cuda_runtime.h>
#include <cuda_bf16.h>
#include <math.h>
#include <stdint.h>

#define NN   50000
#define NV   50001
#define NPAD 50048      // 391 * 128
#define NE   400000
#define IND  256
#define HID  128
#define C2   256
#define OD   64
#define WTOT 139264     // 65536 + 32768 + 32768 + 8192

// ---------------- static device scratch -------------------------------------
__device__ __nv_bfloat16 g_Ahi[(size_t)NPAD * IND];
__device__ __nv_bfloat16 g_Alo[(size_t)NPAD * IND];
__device__ __nv_bfloat16 g_Bthi[WTOT];
__device__ __nv_bfloat16 g_Btlo[WTOT];
__device__ float g_h[(size_t)NV * C2];
__device__ float g_as[NV * 2];
__device__ float g_ad[NV * 2];
__device__ int   g_cnt[NV];
__device__ int   g_cur[NV];
__device__ int   g_rowptr[NV + 1];
__device__ int   g_srcsorted[NE];
__device__ float g_colpart[256 * 256];
__device__ uint32_t g_asmax[3][2];
__device__ float g_vS[C2];
__device__ float g_vden[2];
__device__ int   g_vdone;

__device__ __forceinline__ float lrelu(float x) { return x > 0.f ? x : 0.2f * x; }

// monotone float <-> uint key for atomicMax on signed floats
__device__ __forceinline__ uint32_t fkey(float f) {
    uint32_t b = __float_as_uint(f);
    return b ^ (uint32_t)(((int)b >> 31) | (int)0x80000000);
}
__device__ __forceinline__ float funkey(uint32_t k) {
    uint32_t b = (k & 0x80000000u) ? (k ^ 0x80000000u) : ~k;
    return __uint_as_float(b);
}

__device__ __forceinline__ uint32_t smem_to_u32(const void* p) {
    uint32_t a;
    asm("{ .reg .u64 t; cvta.to.shared.u64 t, %1; cvt.u32.u64 %0, t; }" : "=r"(a) : "l"(p));
    return a;
}

#define SW128(off) ((off) ^ (((off) >> 3) & 0x70))

#define LDSM_X4(r0, r1, r2, r3, addr) \
    asm volatile("ldmatrix.sync.aligned.m8n8.x4.shared.b16 {%0,%1,%2,%3}, [%4];" \
        : "=r"(r0), "=r"(r1), "=r"(r2), "=r"(r3) : "r"(addr))

#define CP16(s, g) asm volatile("cp.async.cg.shared.global [%0], [%1], 16;" :: "r"(s), "l"(g))
#define CPCOMMIT() asm volatile("cp.async.commit_group;" ::: "memory")

__device__ __forceinline__ void mma16816(float* c, const uint32_t* a, uint32_t b0, uint32_t b1) {
    asm volatile("mma.sync.aligned.m16n8k16.row.col.f32.bf16.bf16.f32 "
        "{%0,%1,%2,%3}, {%4,%5,%6,%7}, {%8,%9}, {%0,%1,%2,%3};"
        : "+f"(c[0]), "+f"(c[1]), "+f"(c[2]), "+f"(c[3])
        : "r"(a[0]), "r"(a[1]), "r"(a[2]), "r"(a[3]), "r"(b0), "r"(b1));
}

// ---------------- setup: convert X (hi/lo), column partial sums, zero state --
__global__ void k_setup(const float* __restrict__ X) {   // 256 blocks x 256
    int c = threadIdx.x, b = blockIdx.x;
    float s = 0.f;
    for (int r = b; r < NN; r += 256) {
        float v = X[(size_t)r * IND + c];
        __nv_bfloat16 hi = __float2bfloat16(v);
        g_Ahi[(size_t)r * IND + c] = hi;
        g_Alo[(size_t)r * IND + c] = __float2bfloat16(v - __bfloat162float(hi));
        s += v;
    }
    g_colpart[b * 256 + c] = s;
    int idx = b * 256 + c;
    for (int j = idx; j < NV; j += 65536) { g_cnt[j] = 0; g_cur[j] = 0; }
    uint32_t* am = &g_asmax[0][0];
    if (idx < 6) am[idx] = 0;
    if (idx < C2) g_vS[idx] = 0.f;
    if (idx < 2) g_vden[idx] = 0.f;
    if (idx == 0) g_vdone = 0;
}

// ---------------- prep: all weight conversions + virtual-node row -----------
__global__ void k_prep(const float* __restrict__ W0, const float* __restrict__ W1,
                       const float* __restrict__ W2, const float* __restrict__ Wo) {
    if (blockIdx.x == 544) {                 // vnode input row
        int c = threadIdx.x;                 // 256 threads
        float s = 0.f;
        for (int p = 0; p < 256; p++) s += g_colpart[p * 256 + c];
        float v = s * (1.0f / NN);
        __nv_bfloat16 hi = __float2bfloat16(v);
        g_Ahi[(size_t)NN * IND + c] = hi;
        g_Alo[(size_t)NN * IND + c] = __float2bfloat16(v - __bfloat162float(hi));
        return;
    }
    int i = blockIdx.x * 256 + threadIdx.x;
    const float* W; int K, Ncol, off, loc;
    if      (i < 65536)  { W = W0; K = 256; Ncol = 256; off = 0;      loc = i; }
    else if (i < 98304)  { W = W1; K = 128; Ncol = 256; off = 65536;  loc = i - 65536; }
    else if (i < 131072) { W = W2; K = 128; Ncol = 256; off = 98304;  loc = i - 98304; }
    else if (i < WTOT)   { W = Wo; K = 128; Ncol = 64;  off = 131072; loc = i - 131072; }
    else return;
    int n = loc / K, k = loc % K;
    float v = W[k * Ncol + n];
    __nv_bfloat16 hi = __float2bfloat16(v);
    g_Bthi[off + n * K + k] = hi;
    g_Btlo[off + n * K + k] = __float2bfloat16(v - __bfloat162float(hi));
}

// ---------------- CSR build -------------------------------------------------
__global__ void k_hist(const int* __restrict__ ei) {
    int i = blockIdx.x * blockDim.x + threadIdx.x;
    int stride = gridDim.x * blockDim.x;
    for (int e = i; e < NE; e += stride)
        atomicAdd(&g_cnt[ei[NE + e]], 1);
}

__global__ void k_scan() {
    __shared__ int s[1024];
    int t = threadIdx.x;
    const int CH = (NV + 1023) / 1024;
    int base = t * CH;
    int acc = 0;
    for (int i = 0; i < CH; i++) { int idx = base + i; if (idx < NV) acc += g_cnt[idx]; }
    s[t] = acc;
    __syncthreads();
    for (int off = 1; off < 1024; off <<= 1) {
        int v = (t >= off) ? s[t - off] : 0;
        __syncthreads();
        s[t] += v;
        __syncthreads();
    }
    int prefix = (t == 0) ? 0 : s[t - 1];
    acc = prefix;
    for (int i = 0; i < CH; i++) {
        int idx = base + i;
        if (idx < NV) { g_rowptr[idx] = acc; acc += g_cnt[idx]; }
        else if (idx == NV) { g_rowptr[NV] = acc; }
    }
}

__global__ void k_fill(const int* __restrict__ ei) {
    int i = blockIdx.x * blockDim.x + threadIdx.x;
    int stride = gridDim.x * blockDim.x;
    for (int e = i; e < NE; e += stride) {
        int s = ei[e];
        int d = ei[NE + e];
        int pos = g_rowptr[d] + atomicAdd(&g_cur[d], 1);
        g_srcsorted[pos] = s;
    }
}

// ---------------- HMMA GEMM, cp.async double-buffered, fused alpha epilogue --
// C[M, NTB] = A[M, KTOT] @ Bt^T; hi/lo bf16 3-product split, fp32 accum.
// 512 threads = 16 warps (wm 0..7 x wn 0..1); warp tile 16 rows x NTB/2 cols.
template<int KTOT, int NTB, bool ALPHA, bool BIAS>
__global__ void __launch_bounds__(512, 1) k_hgemm(
    const __nv_bfloat16* __restrict__ Ahi, const __nv_bfloat16* __restrict__ Alo,
    const __nv_bfloat16* __restrict__ Bhi, const __nv_bfloat16* __restrict__ Blo,
    float* __restrict__ Cout, int M,
    const float* __restrict__ aws, const float* __restrict__ awd,
    const float* __restrict__ bias, uint32_t* __restrict__ asmax)
{
    constexpr int NCH = KTOT / 64;
    constexpr int NTW = (NTB / 2) / 8;
    constexpr int NJP = NTW / 2;
    constexpr int STAGE = 32768 + NTB * 256;

    extern __shared__ char smem[];
    uint32_t sb = smem_to_u32(smem);
    int tid = threadIdx.x, wid = tid >> 5, lane = tid & 31;
    int wm = wid >> 1, wn = wid & 1;
    int row0 = blockIdx.x * 128;

    float acc[NTW][4];
#pragma unroll
    for (int nt = 0; nt < NTW; nt++) { acc[nt][0]=0.f; acc[nt][1]=0.f; acc[nt][2]=0.f; acc[nt][3]=0.f; }

    int arow = wm * 16 + ((lane >> 3) & 1) * 8 + (lane & 7);
    uint32_t akoff = ((lane >> 4) & 1) * 16;
    int bnrow = wn * (NTB / 2) + ((lane >> 4) & 1) * 8 + (lane & 7);
    uint32_t bkoff = ((lane >> 3) & 1) * 16;

    for (int ch = 0; ch <= NCH; ch++) {
        if (ch < NCH) {
            uint32_t base = sb + (uint32_t)(ch & 1) * STAGE;
            for (int u = tid; u < 1024; u += 512) {
                int r = u >> 3, c8 = u & 7;
                size_t gidx = (size_t)(row0 + r) * KTOT + ch * 64 + c8 * 8;
                uint32_t soff = SW128((uint32_t)(r * 128 + c8 * 16));
                CP16(base + soff, Ahi + gidx);
                CP16(base + 16384 + soff, Alo + gidx);
            }
            for (int u = tid; u < NTB * 8; u += 512) {
                int r = u >> 3, c8 = u & 7;
                size_t gidx = (size_t)r * KTOT + ch * 64 + c8 * 8;
                uint32_t soff = SW128((uint32_t)(r * 128 + c8 * 16));
                CP16(base + 32768 + soff, Bhi + gidx);
                CP16(base + 32768 + NTB * 128 + soff, Blo + gidx);
            }
            CPCOMMIT();
        }
        if (ch == 0) continue;
        if (ch < NCH) asm volatile("cp.async.wait_group 1;" ::: "memory");
        else         asm volatile("cp.async.wait_group 0;" ::: "memory");
        __syncthreads();
        uint32_t ab = sb + (uint32_t)((ch - 1) & 1) * STAGE;
#pragma unroll
        for (int ks = 0; ks < 4; ks++) {
            uint32_t ah[4], al[4];
            uint32_t aaddr = ab + SW128((uint32_t)(arow * 128 + ks * 32 + akoff));
            LDSM_X4(ah[0], ah[1], ah[2], ah[3], aaddr);
            LDSM_X4(al[0], al[1], al[2], al[3], aaddr + 16384);
#pragma unroll
            for (int jp = 0; jp < NJP; jp++) {
                uint32_t baddr = ab + 32768 + SW128((uint32_t)((bnrow + jp * 16) * 128 + ks * 32 + bkoff));
                uint32_t bh0, bh1, bh2, bh3, bl0, bl1, bl2, bl3;
                LDSM_X4(bh0, bh1, bh2, bh3, baddr);
                LDSM_X4(bl0, bl1, bl2, bl3, baddr + NTB * 128);
                mma16816(acc[2 * jp],     ah, bh0, bh1);
                mma16816(acc[2 * jp],     al, bh0, bh1);
                mma16816(acc[2 * jp],     ah, bl0, bl1);
                mma16816(acc[2 * jp + 1], ah, bh2, bh3);
                mma16816(acc[2 * jp + 1], al, bh2, bh3);
                mma16816(acc[2 * jp + 1], ah, bl2, bl3);
            }
        }
        __syncthreads();
    }

    // epilogue: store C, fused attention logits + global as-max
    int g = lane >> 2, t = lane & 3;
    int gr0 = row0 + wm * 16 + g, gr1 = gr0 + 8;
    float pa0 = 0.f, pa1 = 0.f, pd0 = 0.f, pd1 = 0.f;
#pragma unroll
    for (int nt = 0; nt < NTW; nt++) {
        int gc = wn * (NTB / 2) + nt * 8 + t * 2;
        float c0 = acc[nt][0], c1 = acc[nt][1], c2 = acc[nt][2], c3 = acc[nt][3];
        if (BIAS) {
            float b0 = bias[gc], b1 = bias[gc + 1];
            c0 += b0; c1 += b1; c2 += b0; c3 += b1;
        }
        if (ALPHA) {
            float w0s = aws[gc], w1s = aws[gc + 1], w0d = awd[gc], w1d = awd[gc + 1];
            pa0 += c0 * w0s + c1 * w1s; pd0 += c0 * w0d + c1 * w1d;
            pa1 += c2 * w0s + c3 * w1s; pd1 += c2 * w0d + c3 * w1d;
        }
        if (gr0 < M) *(float2*)&Cout[(size_t)gr0 * NTB + gc] = make_float2(c0, c1);
        if (gr1 < M) *(float2*)&Cout[(size_t)gr1 * NTB + gc] = make_float2(c2, c3);
    }
    if (ALPHA) {
#pragma unroll
        for (int off = 1; off <= 2; off <<= 1) {
            pa0 += __shfl_xor_sync(0xffffffffu, pa0, off);
            pa1 += __shfl_xor_sync(0xffffffffu, pa1, off);
            pd0 += __shfl_xor_sync(0xffffffffu, pd0, off);
            pd1 += __shfl_xor_sync(0xffffffffu, pd1, off);
        }
        float lm = -3.4e38f;
        if (t == 0) {
            if (gr0 < M) { g_as[2 * gr0 + wn] = pa0; g_ad[2 * gr0 + wn] = pd0; lm = pa0; }
            if (gr1 < M) { g_as[2 * gr1 + wn] = pa1; g_ad[2 * gr1 + wn] = pd1; lm = fmaxf(lm, pa1); }
        }
#pragma unroll
        for (int off = 16; off; off >>= 1) lm = fmaxf(lm, __shfl_xor_sync(0xffffffffu, lm, off));
        if (lane == 0) atomicMax(asmax + wn, fkey(lm));
    }
}

// ---------------- vnode accumulate + (last block) LN/GELU finalize ----------
__global__ void k_vacc(int l, const float* __restrict__ b, const float* __restrict__ gam,
                       const float* __restrict__ bet) {
    int gw = (blockIdx.x * blockDim.x + threadIdx.x) >> 5;
    int lane = threadIdx.x & 31;
    int nw = (gridDim.x * blockDim.x) >> 5;
    float adv0 = g_ad[2 * NN], adv1 = g_ad[2 * NN + 1];
    float m0 = lrelu(funkey(g_asmax[l][0]) + adv0);
    float m1 = lrelu(funkey(g_asmax[l][1]) + adv1);
    float acc[8] = {};
    float den0 = 0.f, den1 = 0.f;
    for (int j = gw; j < NV; j += nw) {
        float e0 = __expf(lrelu(g_as[2 * j] + adv0) - m0);
        float e1 = __expf(lrelu(g_as[2 * j + 1] + adv1) - m1);
        den0 += e0; den1 += e1;
        const float* hp = g_h + (size_t)j * C2;
#pragma unroll
        for (int r = 0; r < 8; r++)
            acc[r] = fmaf((r < 4) ? e0 : e1, hp[lane + r * 32], acc[r]);
    }
#pragma unroll
    for (int r = 0; r < 8; r++) atomicAdd(&g_vS[lane + r * 32], acc[r]);
    if (lane == 0) { atomicAdd(&g_vden[0], den0); atomicAdd(&g_vden[1], den1); }

    __threadfence();
    __shared__ int slast;
    if (threadIdx.x == 0) slast = (atomicAdd(&g_vdone, 1) == (int)gridDim.x - 1);
    __syncthreads();
    if (!slast) return;

    // finalize vnode row (threads 0..127), then reset accumulators
    int o = threadIdx.x;
    float v = 0.f;
    if (o < 128) {
        float d0 = g_vden[0] + 1e-16f, d1 = g_vden[1] + 1e-16f;
        v = 0.5f * (g_vS[o] / d0 + g_vS[HID + o] / d1) + b[o];
    }
    __shared__ float ssum[8], ssq[8];
    float ls = (o < 128) ? v : 0.f, lq = (o < 128) ? v * v : 0.f;
#pragma unroll
    for (int off = 16; off; off >>= 1) {
        ls += __shfl_xor_sync(0xffffffffu, ls, off);
        lq += __shfl_xor_sync(0xffffffffu, lq, off);
    }
    int w = o >> 5;
    if ((o & 31) == 0) { ssum[w] = ls; ssq[w] = lq; }
    __syncthreads();
    float ts = ssum[0] + ssum[1] + ssum[2] + ssum[3];
    float tq = ssq[0] + ssq[1] + ssq[2] + ssq[3];
    float mu = ts * (1.0f / HID);
    float var = tq * (1.0f / HID) - mu * mu;
    if (o < 128) {
        float y = (v - mu) * rsqrtf(var + 1e-5f) * gam[o] + bet[o];
        y = 0.5f * y * (1.f + erff(y * 0.70710678118654752f));
        __nv_bfloat16 hi = __float2bfloat16(y);
        g_Ahi[(size_t)NN * HID + o] = hi;
        g_Alo[(size_t)NN * HID + o] = __float2bfloat16(y - __bfloat162float(hi));
    }
    __syncthreads();
    if (o < C2) g_vS[o] = 0.f;
    if (o < 2) g_vden[o] = 0.f;
    if (o == 0) g_vdone = 0;
}

// ---------------- per-node aggregation + LN + GELU (warp/node, single pass) --
__global__ void k_nodeagg(int l, const float* __restrict__ b, const float* __restrict__ gam,
                          const float* __restrict__ bet) {
    int i = (blockIdx.x * blockDim.x + threadIdx.x) >> 5;
    int lane = threadIdx.x & 31;
    if (i >= NN) return;
    float ad0 = g_ad[2 * i], ad1 = g_ad[2 * i + 1];
    float m0 = lrelu(funkey(g_asmax[l][0]) + ad0);
    float m1 = lrelu(funkey(g_asmax[l][1]) + ad1);

    float acc[8] = {};
    float den0, den1;
    {   // self loop + vnode->node edge
        float c0 = __expf(lrelu(g_as[2 * i] + ad0) - m0);
        float c1 = __expf(lrelu(g_as[2 * i + 1] + ad1) - m1);
        den0 = c0; den1 = c1;
        const float* hp = g_h + (size_t)i * C2;
#pragma unroll
        for (int r = 0; r < 8; r++) acc[r] = fmaf((r < 4) ? c0 : c1, hp[lane + r * 32], acc[r]);
        c0 = __expf(lrelu(g_as[2 * NN] + ad0) - m0);
        c1 = __expf(lrelu(g_as[2 * NN + 1] + ad1) - m1);
        den0 += c0; den1 += c1;
        const float* hv = g_h + (size_t)NN * C2;
#pragma unroll
        for (int r = 0; r < 8; r++) acc[r] = fmaf((r < 4) ? c0 : c1, hv[lane + r * 32], acc[r]);
    }
    int beg = g_rowptr[i], end = g_rowptr[i + 1];
    if (beg < end) {
        int s = g_srcsorted[beg];
        float as0 = g_as[2 * s], as1 = g_as[2 * s + 1];
        for (int e = beg; e < end; e++) {
            int scur = s;
            float ca0 = as0, ca1 = as1;
            if (e + 1 < end) {                   // prefetch next edge
                s = g_srcsorted[e + 1];
                as0 = g_as[2 * s]; as1 = g_as[2 * s + 1];
            }
            float c0 = __expf(lrelu(ca0 + ad0) - m0);
            float c1 = __expf(lrelu(ca1 + ad1) - m1);
            den0 += c0; den1 += c1;
            const float* hp = g_h + (size_t)scur * C2;
#pragma unroll
            for (int r = 0; r < 8; r++) acc[r] = fmaf((r < 4) ? c0 : c1, hp[lane + r * 32], acc[r]);
        }
    }

    float inv0 = 0.5f / (den0 + 1e-16f);
    float inv1 = 0.5f / (den1 + 1e-16f);
    float v[4], lsum = 0.f, lsq = 0.f;
#pragma unroll
    for (int r = 0; r < 4; r++) {
        int o = lane + r * 32;
        v[r] = acc[r] * inv0 + acc[4 + r] * inv1 + b[o];
        lsum += v[r];
        lsq = fmaf(v[r], v[r], lsq);
    }
#pragma unroll
    for (int off = 16; off; off >>= 1) {
        lsum += __shfl_xor_sync(0xffffffffu, lsum, off);
        lsq += __shfl_xor_sync(0xffffffffu, lsq, off);
    }
    float mu = lsum * (1.0f / HID);
    float var = lsq * (1.0f / HID) - mu * mu;
    float rstd = rsqrtf(var + 1e-5f);
#pragma unroll
    for (int r = 0; r < 4; r++) {
        int o = lane + r * 32;
        float y = (v[r] - mu) * rstd * gam[o] + bet[o];
        y = 0.5f * y * (1.f + erff(y * 0.70710678118654752f));
        __nv_bfloat16 hi = __float2bfloat16(y);
        g_Ahi[(size_t)i * HID + o] = hi;
        g_Alo[(size_t)i * HID + o] = __float2bfloat16(y - __bfloat162float(hi));
    }
}

// ---------------- host orchestration ----------------------------------------
extern "C" void kernel_launch(void* const* d_in, const int* in_sizes, int n_in,
                              void* d_out, int out_size) {
    const float* X  = (const float*)d_in[0];
    const int*   ei = (const int*)d_in[1];
    const float* W[3]   = { (const float*)d_in[3],  (const float*)d_in[9],  (const float*)d_in[15] };
    const float* a_s[3] = { (const float*)d_in[4],  (const float*)d_in[10], (const float*)d_in[16] };
    const float* a_d[3] = { (const float*)d_in[5],  (const float*)d_in[11], (const float*)d_in[17] };
    const float* bb[3]  = { (const float*)d_in[6],  (const float*)d_in[12], (const float*)d_in[18] };
    const float* gg[3]  = { (const float*)d_in[7],  (const float*)d_in[13], (const float*)d_in[19] };
    const float* be[3]  = { (const float*)d_in[8],  (const float*)d_in[14], (const float*)d_in[20] };
    const float* Wout = (const float*)d_in[21];
    const float* bout = (const float*)d_in[22];

    __nv_bfloat16 *pAhi, *pAlo, *pBhi, *pBlo;
    float* p_h;
    uint32_t* p_am;
    cudaGetSymbolAddress((void**)&pAhi, g_Ahi);
    cudaGetSymbolAddress((void**)&pAlo, g_Alo);
    cudaGetSymbolAddress((void**)&pBhi, g_Bthi);
    cudaGetSymbolAddress((void**)&pBlo, g_Btlo);
    cudaGetSymbolAddress((void**)&p_h,  g_h);
    cudaGetSymbolAddress((void**)&p_am, g_asmax);

    const int SM256 = 2 * (32768 + 256 * 256);   // 196608
    const int SM64  = 2 * (32768 + 64 * 256);    // 98304
    cudaFuncSetAttribute(k_hgemm<256, 256, true,  false>, cudaFuncAttributeMaxDynamicSharedMemorySize, SM256);
    cudaFuncSetAttribute(k_hgemm<128, 256, true,  false>, cudaFuncAttributeMaxDynamicSharedMemorySize, SM256);
    cudaFuncSetAttribute(k_hgemm<128, 64,  false, true>,  cudaFuncAttributeMaxDynamicSharedMemorySize, SM64);

    const int NBLK = NPAD / 128;   // 391

    k_setup<<<256, 256>>>(X);                                        // 0
    k_prep<<<545, 256>>>(W[0], W[1], W[2], Wout);                    // 1
    k_hist<<<1024, 256>>>(ei);                                       // 2
    k_scan<<<1, 1024>>>();                                           // 3
    k_fill<<<1024, 256>>>(ei);                                       // 4

    const int WOFF[4] = { 0, 65536, 98304, 131072 };

    // layer 0 (profiled launch #5)
    k_hgemm<256, 256, true, false><<<NBLK, 512, SM256>>>(
        pAhi, pAlo, pBhi + WOFF[0], pBlo + WOFF[0], p_h, NV, a_s[0], a_d[0], nullptr, p_am + 0);
    k_vacc<<<256, 256>>>(0, bb[0], gg[0], be[0]);
    k_nodeagg<<<(NN * 32 + 255) / 256, 256>>>(0, bb[0], gg[0], be[0]);

    for (int l = 1; l < 3; l++) {
        k_hgemm<128, 256, true, false><<<NBLK, 512, SM256>>>(
            pAhi, pAlo, pBhi + WOFF[l], pBlo + WOFF[l], p_h, NV, a_s[l], a_d[l], nullptr, p_am + 2 * l);
        k_vacc<<<256, 256>>>(l, bb[l], gg[l], be[l]);
        k_nodeagg<<<(NN * 32 + 255) / 256, 256>>>(l, bb[l], gg[l], be[l]);
    }

    k_hgemm<128, 64, false, true><<<NBLK, 512, SM64>>>(
        pAhi, pAlo, pBhi + WOFF[3], pBlo + WOFF[3], (float*)d_out, NN, nullptr, nullptr, bout, nullptr);
}

// round 5
// speedup vs baseline: 2.2378x; 1.2703x over previous
#include <cuda_runtime.h>
#include <cuda_bf16.h>
#include <math.h>
#include <stdint.h>

#define NN   50000
#define NV   50001
#define NPAD 50048      // 391 * 128
#define NE   400000
#define IND  256
#define HID  128
#define C2   256
#define OD   64
#define WTOT 139264     // 65536 + 32768 + 32768 + 8192
#define SCHUNK 1024
#define SNB   49        // ceil(NV / 1024)

// ---------------- static device scratch -------------------------------------
__device__ __nv_bfloat16 g_Ahi[(size_t)NPAD * IND];
__device__ __nv_bfloat16 g_Alo[(size_t)NPAD * IND];
__device__ __nv_bfloat16 g_Bthi[WTOT];
__device__ __nv_bfloat16 g_Btlo[WTOT];
__device__ float g_h[(size_t)NV * C2];
__device__ float g_as[NV * 2];
__device__ float g_ad[NV * 2];
__device__ int   g_cnt[SNB * SCHUNK];
__device__ int   g_cur[NV];
__device__ int   g_scan[SNB * SCHUNK];   // per-chunk exclusive scan
__device__ int   g_btot[SNB];
__device__ int   g_boff[SNB];
__device__ int   g_srcsorted[NE];
__device__ float g_colpart[256 * 256];
__device__ uint32_t g_asmax[3][2];
__device__ float g_vS[C2];
__device__ float g_vden[2];
__device__ int   g_vdone;

__device__ __forceinline__ float lrelu(float x) { return x > 0.f ? x : 0.2f * x; }

__device__ __forceinline__ uint32_t fkey(float f) {
    uint32_t b = __float_as_uint(f);
    return b ^ (uint32_t)(((int)b >> 31) | (int)0x80000000);
}
__device__ __forceinline__ float funkey(uint32_t k) {
    uint32_t b = (k & 0x80000000u) ? (k ^ 0x80000000u) : ~k;
    return __uint_as_float(b);
}

__device__ __forceinline__ uint32_t smem_to_u32(const void* p) {
    uint32_t a;
    asm("{ .reg .u64 t; cvta.to.shared.u64 t, %1; cvt.u32.u64 %0, t; }" : "=r"(a) : "l"(p));
    return a;
}

#define SW128(off) ((off) ^ (((off) >> 3) & 0x70))

#define LDSM_X4(r0, r1, r2, r3, addr) \
    asm volatile("ldmatrix.sync.aligned.m8n8.x4.shared.b16 {%0,%1,%2,%3}, [%4];" \
        : "=r"(r0), "=r"(r1), "=r"(r2), "=r"(r3) : "r"(addr))

#define CP16(s, g) asm volatile("cp.async.cg.shared.global [%0], [%1], 16;" :: "r"(s), "l"(g))
#define CPCOMMIT() asm volatile("cp.async.commit_group;" ::: "memory")

__device__ __forceinline__ void mma16816(float* c, const uint32_t* a, uint32_t b0, uint32_t b1) {
    asm volatile("mma.sync.aligned.m16n8k16.row.col.f32.bf16.bf16.f32 "
        "{%0,%1,%2,%3}, {%4,%5,%6,%7}, {%8,%9}, {%0,%1,%2,%3};"
        : "+f"(c[0]), "+f"(c[1]), "+f"(c[2]), "+f"(c[3])
        : "r"(a[0]), "r"(a[1]), "r"(a[2]), "r"(a[3]), "r"(b0), "r"(b1));
}

// ---------------- setup -------------------------------------------------------
__global__ void k_setup(const float* __restrict__ X) {   // 256 blocks x 256
    int c = threadIdx.x, b = blockIdx.x;
    float s = 0.f;
    for (int r = b; r < NN; r += 256) {
        float v = X[(size_t)r * IND + c];
        __nv_bfloat16 hi = __float2bfloat16(v);
        g_Ahi[(size_t)r * IND + c] = hi;
        g_Alo[(size_t)r * IND + c] = __float2bfloat16(v - __bfloat162float(hi));
        s += v;
    }
    g_colpart[b * 256 + c] = s;
    int idx = b * 256 + c;
    for (int j = idx; j < SNB * SCHUNK; j += 65536) g_cnt[j] = 0;
    for (int j = idx; j < NV; j += 65536) g_cur[j] = 0;
    uint32_t* am = &g_asmax[0][0];
    if (idx < 6) am[idx] = 0;
    if (idx < C2) g_vS[idx] = 0.f;
    if (idx < 2) g_vden[idx] = 0.f;
    if (idx == 0) g_vdone = 0;
}

// ---------------- prep: weight conversions + virtual-node row ----------------
__global__ void k_prep(const float* __restrict__ W0, const float* __restrict__ W1,
                       const float* __restrict__ W2, const float* __restrict__ Wo) {
    if (blockIdx.x == 544) {
        int c = threadIdx.x;
        float s = 0.f;
        for (int p = 0; p < 256; p++) s += g_colpart[p * 256 + c];
        float v = s * (1.0f / NN);
        __nv_bfloat16 hi = __float2bfloat16(v);
        g_Ahi[(size_t)NN * IND + c] = hi;
        g_Alo[(size_t)NN * IND + c] = __float2bfloat16(v - __bfloat162float(hi));
        return;
    }
    int i = blockIdx.x * 256 + threadIdx.x;
    const float* W; int K, Ncol, off, loc;
    if      (i < 65536)  { W = W0; K = 256; Ncol = 256; off = 0;      loc = i; }
    else if (i < 98304)  { W = W1; K = 128; Ncol = 256; off = 65536;  loc = i - 65536; }
    else if (i < 131072) { W = W2; K = 128; Ncol = 256; off = 98304;  loc = i - 98304; }
    else if (i < WTOT)   { W = Wo; K = 128; Ncol = 64;  off = 131072; loc = i - 131072; }
    else return;
    int n = loc / K, k = loc % K;
    float v = W[k * Ncol + n];
    __nv_bfloat16 hi = __float2bfloat16(v);
    g_Bthi[off + n * K + k] = hi;
    g_Btlo[off + n * K + k] = __float2bfloat16(v - __bfloat162float(hi));
}

// ---------------- CSR build ---------------------------------------------------
__global__ void k_hist(const int* __restrict__ ei) {
    int i = blockIdx.x * blockDim.x + threadIdx.x;
    int stride = gridDim.x * blockDim.x;
    for (int e = i; e < NE; e += stride)
        atomicAdd(&g_cnt[ei[NE + e]], 1);
}

// block-local exclusive scan over 1024-element chunks
__global__ void k_scan1() {        // SNB blocks x 1024
    int b = blockIdx.x, t = threadIdx.x, lane = t & 31, w = t >> 5;
    int idx = b * SCHUNK + t;
    int v = g_cnt[idx];
    int x = v;
#pragma unroll
    for (int off = 1; off < 32; off <<= 1) {
        int y = __shfl_up_sync(0xffffffffu, x, off);
        if (lane >= off) x += y;
    }
    __shared__ int wt[32];
    if (lane == 31) wt[w] = x;
    __syncthreads();
    if (w == 0) {
        int z = wt[lane];
#pragma unroll
        for (int off = 1; off < 32; off <<= 1) {
            int y = __shfl_up_sync(0xffffffffu, z, off);
            if (lane >= off) z += y;
        }
        wt[lane] = z;
    }
    __syncthreads();
    int excl = x - v + (w ? wt[w - 1] : 0);
    g_scan[idx] = excl;
    if (t == 0) g_btot[b] = wt[31];
}

__global__ void k_scan2() {        // 1 block x 64
    __shared__ int s[SNB];
    int t = threadIdx.x;
    if (t < SNB) s[t] = g_btot[t];
    __syncthreads();
    if (t == 0) {
        int acc = 0;
        for (int i = 0; i < SNB; i++) { g_boff[i] = acc; acc += s[i]; }
    }
}

__device__ __forceinline__ int rowptr_of(int i) {
    return g_scan[i] + g_boff[i >> 10];
}

__global__ void k_fill(const int* __restrict__ ei) {
    int i = blockIdx.x * blockDim.x + threadIdx.x;
    int stride = gridDim.x * blockDim.x;
    for (int e = i; e < NE; e += stride) {
        int s = ei[e];
        int d = ei[NE + e];
        int pos = rowptr_of(d) + atomicAdd(&g_cur[d], 1);
        g_srcsorted[pos] = s;
    }
}

// ---------------- HMMA GEMM (cp.async double-buffered, fused alpha epilogue) --
template<int KTOT, int NTB, bool ALPHA, bool BIAS>
__global__ void __launch_bounds__(512, 1) k_hgemm(
    const __nv_bfloat16* __restrict__ Ahi, const __nv_bfloat16* __restrict__ Alo,
    const __nv_bfloat16* __restrict__ Bhi, const __nv_bfloat16* __restrict__ Blo,
    float* __restrict__ Cout, int M,
    const float* __restrict__ aws, const float* __restrict__ awd,
    const float* __restrict__ bias, uint32_t* __restrict__ asmax)
{
    constexpr int NCH = KTOT / 64;
    constexpr int NTW = (NTB / 2) / 8;
    constexpr int NJP = NTW / 2;
    constexpr int STAGE = 32768 + NTB * 256;

    extern __shared__ char smem[];
    uint32_t sb = smem_to_u32(smem);
    int tid = threadIdx.x, wid = tid >> 5, lane = tid & 31;
    int wm = wid >> 1, wn = wid & 1;
    int row0 = blockIdx.x * 128;

    float acc[NTW][4];
#pragma unroll
    for (int nt = 0; nt < NTW; nt++) { acc[nt][0]=0.f; acc[nt][1]=0.f; acc[nt][2]=0.f; acc[nt][3]=0.f; }

    int arow = wm * 16 + ((lane >> 3) & 1) * 8 + (lane & 7);
    uint32_t akoff = ((lane >> 4) & 1) * 16;
    int bnrow = wn * (NTB / 2) + ((lane >> 4) & 1) * 8 + (lane & 7);
    uint32_t bkoff = ((lane >> 3) & 1) * 16;

    for (int ch = 0; ch <= NCH; ch++) {
        if (ch < NCH) {
            uint32_t base = sb + (uint32_t)(ch & 1) * STAGE;
            for (int u = tid; u < 1024; u += 512) {
                int r = u >> 3, c8 = u & 7;
                size_t gidx = (size_t)(row0 + r) * KTOT + ch * 64 + c8 * 8;
                uint32_t soff = SW128((uint32_t)(r * 128 + c8 * 16));
                CP16(base + soff, Ahi + gidx);
                CP16(base + 16384 + soff, Alo + gidx);
            }
            for (int u = tid; u < NTB * 8; u += 512) {
                int r = u >> 3, c8 = u & 7;
                size_t gidx = (size_t)r * KTOT + ch * 64 + c8 * 8;
                uint32_t soff = SW128((uint32_t)(r * 128 + c8 * 16));
                CP16(base + 32768 + soff, Bhi + gidx);
                CP16(base + 32768 + NTB * 128 + soff, Blo + gidx);
            }
            CPCOMMIT();
        }
        if (ch == 0) continue;
        if (ch < NCH) asm volatile("cp.async.wait_group 1;" ::: "memory");
        else         asm volatile("cp.async.wait_group 0;" ::: "memory");
        __syncthreads();
        uint32_t ab = sb + (uint32_t)((ch - 1) & 1) * STAGE;
#pragma unroll
        for (int ks = 0; ks < 4; ks++) {
            uint32_t ah[4], al[4];
            uint32_t aaddr = ab + SW128((uint32_t)(arow * 128 + ks * 32 + akoff));
            LDSM_X4(ah[0], ah[1], ah[2], ah[3], aaddr);
            LDSM_X4(al[0], al[1], al[2], al[3], aaddr + 16384);
#pragma unroll
            for (int jp = 0; jp < NJP; jp++) {
                uint32_t baddr = ab + 32768 + SW128((uint32_t)((bnrow + jp * 16) * 128 + ks * 32 + bkoff));
                uint32_t bh0, bh1, bh2, bh3, bl0, bl1, bl2, bl3;
                LDSM_X4(bh0, bh1, bh2, bh3, baddr);
                LDSM_X4(bl0, bl1, bl2, bl3, baddr + NTB * 128);
                mma16816(acc[2 * jp],     ah, bh0, bh1);
                mma16816(acc[2 * jp],     al, bh0, bh1);
                mma16816(acc[2 * jp],     ah, bl0, bl1);
                mma16816(acc[2 * jp + 1], ah, bh2, bh3);
                mma16816(acc[2 * jp + 1], al, bh2, bh3);
                mma16816(acc[2 * jp + 1], ah, bl2, bl3);
            }
        }
        __syncthreads();
    }

    int g = lane >> 2, t = lane & 3;
    int gr0 = row0 + wm * 16 + g, gr1 = gr0 + 8;
    float pa0 = 0.f, pa1 = 0.f, pd0 = 0.f, pd1 = 0.f;
#pragma unroll
    for (int nt = 0; nt < NTW; nt++) {
        int gc = wn * (NTB / 2) + nt * 8 + t * 2;
        float c0 = acc[nt][0], c1 = acc[nt][1], c2 = acc[nt][2], c3 = acc[nt][3];
        if (BIAS) {
            float b0 = bias[gc], b1 = bias[gc + 1];
            c0 += b0; c1 += b1; c2 += b0; c3 += b1;
        }
        if (ALPHA) {
            float w0s = aws[gc], w1s = aws[gc + 1], w0d = awd[gc], w1d = awd[gc + 1];
            pa0 += c0 * w0s + c1 * w1s; pd0 += c0 * w0d + c1 * w1d;
            pa1 += c2 * w0s + c3 * w1s; pd1 += c2 * w0d + c3 * w1d;
        }
        if (gr0 < M) *(float2*)&Cout[(size_t)gr0 * NTB + gc] = make_float2(c0, c1);
        if (gr1 < M) *(float2*)&Cout[(size_t)gr1 * NTB + gc] = make_float2(c2, c3);
    }
    if (ALPHA) {
#pragma unroll
        for (int off = 1; off <= 2; off <<= 1) {
            pa0 += __shfl_xor_sync(0xffffffffu, pa0, off);
            pa1 += __shfl_xor_sync(0xffffffffu, pa1, off);
            pd0 += __shfl_xor_sync(0xffffffffu, pd0, off);
            pd1 += __shfl_xor_sync(0xffffffffu, pd1, off);
        }
        float lm = -3.4e38f;
        if (t == 0) {
            if (gr0 < M) { g_as[2 * gr0 + wn] = pa0; g_ad[2 * gr0 + wn] = pd0; lm = pa0; }
            if (gr1 < M) { g_as[2 * gr1 + wn] = pa1; g_ad[2 * gr1 + wn] = pd1; lm = fmaxf(lm, pa1); }
        }
#pragma unroll
        for (int off = 16; off; off >>= 1) lm = fmaxf(lm, __shfl_xor_sync(0xffffffffu, lm, off));
        if (lane == 0) atomicMax(asmax + wn, fkey(lm));
    }
}

// ---------------- merged: vnode accumulate (blocks 0..255) + node agg --------
#define VB 256
__global__ void k_agg(int l, const float* __restrict__ b, const float* __restrict__ gam,
                      const float* __restrict__ bet) {
    int tid = threadIdx.x, wid = tid >> 5, lane = tid & 31;
    float m0g = funkey(g_asmax[l][0]), m1g = funkey(g_asmax[l][1]);

    if (blockIdx.x < VB) {
        // ---- vnode accumulation role ----
        float adv0 = g_ad[2 * NN], adv1 = g_ad[2 * NN + 1];
        float m0 = lrelu(m0g + adv0), m1 = lrelu(m1g + adv1);
        int gw = blockIdx.x * 8 + wid;
        float acc[8] = {};
        float den0 = 0.f, den1 = 0.f;
        for (int j = gw; j < NV; j += VB * 8) {
            float e0 = __expf(lrelu(g_as[2 * j] + adv0) - m0);
            float e1 = __expf(lrelu(g_as[2 * j + 1] + adv1) - m1);
            den0 += e0; den1 += e1;
            const float* hp = g_h + (size_t)j * C2;
#pragma unroll
            for (int r = 0; r < 8; r++)
                acc[r] = fmaf((r < 4) ? e0 : e1, hp[lane + r * 32], acc[r]);
        }
        __shared__ float buf[C2];
        __shared__ float sden[2];
        if (tid < C2) buf[tid] = 0.f;
        if (tid < 2) sden[tid] = 0.f;
        __syncthreads();
#pragma unroll
        for (int r = 0; r < 8; r++) atomicAdd(&buf[lane + r * 32], acc[r]);
        if (lane == 0) { atomicAdd(&sden[0], den0); atomicAdd(&sden[1], den1); }
        __syncthreads();
        if (tid < C2) atomicAdd(&g_vS[tid], buf[tid]);
        if (tid < 2) atomicAdd(&g_vden[tid], sden[tid]);

        __threadfence();
        __shared__ int slast;
        if (tid == 0) slast = (atomicAdd(&g_vdone, 1) == VB - 1);
        __syncthreads();
        if (!slast) return;

        int o = tid;
        float v = 0.f;
        if (o < 128) {
            float d0 = g_vden[0] + 1e-16f, d1 = g_vden[1] + 1e-16f;
            v = 0.5f * (g_vS[o] / d0 + g_vS[HID + o] / d1) + b[o];
        }
        __shared__ float ssum[8], ssq[8];
        float ls = (o < 128) ? v : 0.f, lq = (o < 128) ? v * v : 0.f;
#pragma unroll
        for (int off = 16; off; off >>= 1) {
            ls += __shfl_xor_sync(0xffffffffu, ls, off);
            lq += __shfl_xor_sync(0xffffffffu, lq, off);
        }
        if (lane == 0) { ssum[wid] = ls; ssq[wid] = lq; }
        __syncthreads();
        float ts = ssum[0] + ssum[1] + ssum[2] + ssum[3];
        float tq = ssq[0] + ssq[1] + ssq[2] + ssq[3];
        float mu = ts * (1.0f / HID);
        float var = tq * (1.0f / HID) - mu * mu;
        if (o < 128) {
            float y = (v - mu) * rsqrtf(var + 1e-5f) * gam[o] + bet[o];
            y = 0.5f * y * (1.f + erff(y * 0.70710678118654752f));
            __nv_bfloat16 hi = __float2bfloat16(y);
            g_Ahi[(size_t)NN * HID + o] = hi;
            g_Alo[(size_t)NN * HID + o] = __float2bfloat16(y - __bfloat162float(hi));
        }
        __syncthreads();
        if (o < C2) g_vS[o] = 0.f;
        if (o < 2) g_vden[o] = 0.f;
        if (o == 0) g_vdone = 0;
        return;
    }

    // ---- per-node aggregation role (warp per node) ----
    int i = (blockIdx.x - VB) * 8 + wid;
    if (i >= NN) return;
    float ad0 = g_ad[2 * i], ad1 = g_ad[2 * i + 1];
    float m0 = lrelu(m0g + ad0), m1 = lrelu(m1g + ad1);

    float acc[8] = {};
    float den0, den1;
    {
        float c0 = __expf(lrelu(g_as[2 * i] + ad0) - m0);
        float c1 = __expf(lrelu(g_as[2 * i + 1] + ad1) - m1);
        den0 = c0; den1 = c1;
        const float* hp = g_h + (size_t)i * C2;
#pragma unroll
        for (int r = 0; r < 8; r++) acc[r] = fmaf((r < 4) ? c0 : c1, hp[lane + r * 32], acc[r]);
        c0 = __expf(lrelu(g_as[2 * NN] + ad0) - m0);
        c1 = __expf(lrelu(g_as[2 * NN + 1] + ad1) - m1);
        den0 += c0; den1 += c1;
        const float* hv = g_h + (size_t)NN * C2;
#pragma unroll
        for (int r = 0; r < 8; r++) acc[r] = fmaf((r < 4) ? c0 : c1, hv[lane + r * 32], acc[r]);
    }
    int beg = rowptr_of(i), end = rowptr_of(i + 1);
    if (beg < end) {
        int s = g_srcsorted[beg];
        float as0 = g_as[2 * s], as1 = g_as[2 * s + 1];
        for (int e = beg; e < end; e++) {
            int scur = s;
            float ca0 = as0, ca1 = as1;
            if (e + 1 < end) {
                s = g_srcsorted[e + 1];
                as0 = g_as[2 * s]; as1 = g_as[2 * s + 1];
            }
            float c0 = __expf(lrelu(ca0 + ad0) - m0);
            float c1 = __expf(lrelu(ca1 + ad1) - m1);
            den0 += c0; den1 += c1;
            const float* hp = g_h + (size_t)scur * C2;
#pragma unroll
            for (int r = 0; r < 8; r++) acc[r] = fmaf((r < 4) ? c0 : c1, hp[lane + r * 32], acc[r]);
        }
    }

    float inv0 = 0.5f / (den0 + 1e-16f);
    float inv1 = 0.5f / (den1 + 1e-16f);
    float v[4], lsum = 0.f, lsq = 0.f;
#pragma unroll
    for (int r = 0; r < 4; r++) {
        int o = lane + r * 32;
        v[r] = acc[r] * inv0 + acc[4 + r] * inv1 + b[o];
        lsum += v[r];
        lsq = fmaf(v[r], v[r], lsq);
    }
#pragma unroll
    for (int off = 16; off; off >>= 1) {
        lsum += __shfl_xor_sync(0xffffffffu, lsum, off);
        lsq += __shfl_xor_sync(0xffffffffu, lsq, off);
    }
    float mu = lsum * (1.0f / HID);
    float var = lsq * (1.0f / HID) - mu * mu;
    float rstd = rsqrtf(var + 1e-5f);
#pragma unroll
    for (int r = 0; r < 4; r++) {
        int o = lane + r * 32;
        float y = (v[r] - mu) * rstd * gam[o] + bet[o];
        y = 0.5f * y * (1.f + erff(y * 0.70710678118654752f));
        __nv_bfloat16 hi = __float2bfloat16(y);
        g_Ahi[(size_t)i * HID + o] = hi;
        g_Alo[(size_t)i * HID + o] = __float2bfloat16(y - __bfloat162float(hi));
    }
}

// ---------------- host orchestration ----------------------------------------
extern "C" void kernel_launch(void* const* d_in, const int* in_sizes, int n_in,
                              void* d_out, int out_size) {
    const float* X  = (const float*)d_in[0];
    const int*   ei = (const int*)d_in[1];
    const float* W[3]   = { (const float*)d_in[3],  (const float*)d_in[9],  (const float*)d_in[15] };
    const float* a_s[3] = { (const float*)d_in[4],  (const float*)d_in[10], (const float*)d_in[16] };
    const float* a_d[3] = { (const float*)d_in[5],  (const float*)d_in[11], (const float*)d_in[17] };
    const float* bb[3]  = { (const float*)d_in[6],  (const float*)d_in[12], (const float*)d_in[18] };
    const float* gg[3]  = { (const float*)d_in[7],  (const float*)d_in[13], (const float*)d_in[19] };
    const float* be[3]  = { (const float*)d_in[8],  (const float*)d_in[14], (const float*)d_in[20] };
    const float* Wout = (const float*)d_in[21];
    const float* bout = (const float*)d_in[22];

    __nv_bfloat16 *pAhi, *pAlo, *pBhi, *pBlo;
    float* p_h;
    uint32_t* p_am;
    cudaGetSymbolAddress((void**)&pAhi, g_Ahi);
    cudaGetSymbolAddress((void**)&pAlo, g_Alo);
    cudaGetSymbolAddress((void**)&pBhi, g_Bthi);
    cudaGetSymbolAddress((void**)&pBlo, g_Btlo);
    cudaGetSymbolAddress((void**)&p_h,  g_h);
    cudaGetSymbolAddress((void**)&p_am, g_asmax);

    const int SM256 = 2 * (32768 + 256 * 256);   // 196608
    const int SM64  = 2 * (32768 + 64 * 256);    // 98304
    cudaFuncSetAttribute(k_hgemm<256, 256, true,  false>, cudaFuncAttributeMaxDynamicSharedMemorySize, SM256);
    cudaFuncSetAttribute(k_hgemm<128, 256, true,  false>, cudaFuncAttributeMaxDynamicSharedMemorySize, SM256);
    cudaFuncSetAttribute(k_hgemm<128, 64,  false, true>,  cudaFuncAttributeMaxDynamicSharedMemorySize, SM64);

    const int NBLK = NPAD / 128;   // 391
    const int AGGB = VB + (NN + 7) / 8;   // 256 + 6250
    const int WOFF[4] = { 0, 65536, 98304, 131072 };

    k_setup<<<256, 256>>>(X);                          // 0
    k_prep<<<545, 256>>>(W[0], W[1], W[2], Wout);      // 1
    k_hist<<<1024, 256>>>(ei);                         // 2
    k_scan1<<<SNB, 1024>>>();                          // 3
    k_scan2<<<1, 64>>>();                              // 4
    // layer-0 GEMM is launch #5 (profiled); independent of fill
    k_hgemm<256, 256, true, false><<<NBLK, 512, SM256>>>(
        pAhi, pAlo, pBhi + WOFF[0], pBlo + WOFF[0], p_h, NV, a_s[0], a_d[0], nullptr, p_am + 0);
    k_fill<<<1024, 256>>>(ei);                         // 6
    k_agg<<<AGGB, 256>>>(0, bb[0], gg[0], be[0]);

    for (int l = 1; l < 3; l++) {
        k_hgemm<128, 256, true, false><<<NBLK, 512, SM256>>>(
            pAhi, pAlo, pBhi + WOFF[l], pBlo + WOFF[l], p_h, NV, a_s[l], a_d[l], nullptr, p_am + 2 * l);
        k_agg<<<AGGB, 256>>>(l, bb[l], gg[l], be[l]);
    }

    k_hgemm<128, 64, false, true><<<NBLK, 512, SM64>>>(
        pAhi, pAlo, pBhi + WOFF[3], pBlo + WOFF[3], (float*)d_out, NN, nullptr, nullptr, bout, nullptr);
}

// round 6
// speedup vs baseline: 2.3507x; 1.0505x over previous
#include <cuda_runtime.h>
#include <cuda_fp16.h>
#include <math.h>
#include <stdint.h>

#define NN   50000
#define NV   50001
#define NPAD 50048      // 391 * 128
#define NE   400000
#define IND  256
#define HID  128
#define C2   256
#define OD   64
#define WTOT 139264     // 65536 + 32768 + 32768 + 8192
#define SCHUNK 1024
#define SNB   49

// ---------------- static device scratch -------------------------------------
__device__ __half g_Ahi[(size_t)NPAD * IND];
__device__ __half g_Alo[(size_t)NPAD * IND];
__device__ __half g_Bt[WTOT];                 // B^T fp16 (N-major, k-contig)
__device__ float g_h[(size_t)NV * C2];
__device__ float g_as[NV * 2];
__device__ float g_ad[NV * 2];
__device__ int   g_cnt[SNB * SCHUNK];
__device__ int   g_cur[NV];
__device__ int   g_scan[SNB * SCHUNK];
__device__ int   g_btot[SNB];
__device__ int   g_boff[SNB];
__device__ int   g_srcsorted[NE];
__device__ float g_colpart[256 * 256];
__device__ uint32_t g_asmax[3][2];
__device__ float g_vS[C2];
__device__ float g_vden[2];
__device__ int   g_vdone;

__device__ __forceinline__ float lrelu(float x) { return x > 0.f ? x : 0.2f * x; }

__device__ __forceinline__ uint32_t fkey(float f) {
    uint32_t b = __float_as_uint(f);
    return b ^ (uint32_t)(((int)b >> 31) | (int)0x80000000);
}
__device__ __forceinline__ float funkey(uint32_t k) {
    uint32_t b = (k & 0x80000000u) ? (k ^ 0x80000000u) : ~k;
    return __uint_as_float(b);
}

__device__ __forceinline__ uint32_t smem_to_u32(const void* p) {
    uint32_t a;
    asm("{ .reg .u64 t; cvta.to.shared.u64 t, %1; cvt.u32.u64 %0, t; }" : "=r"(a) : "l"(p));
    return a;
}

#define SW128(off) ((off) ^ (((off) >> 3) & 0x70))

#define LDSM_X4(r0, r1, r2, r3, addr) \
    asm volatile("ldmatrix.sync.aligned.m8n8.x4.shared.b16 {%0,%1,%2,%3}, [%4];" \
        : "=r"(r0), "=r"(r1), "=r"(r2), "=r"(r3) : "r"(addr))

#define CP16(s, g) asm volatile("cp.async.cg.shared.global [%0], [%1], 16;" :: "r"(s), "l"(g))
#define CPCOMMIT() asm volatile("cp.async.commit_group;" ::: "memory")

__device__ __forceinline__ void mma16816(float* c, const uint32_t* a, uint32_t b0, uint32_t b1) {
    asm volatile("mma.sync.aligned.m16n8k16.row.col.f32.f16.f16.f32 "
        "{%0,%1,%2,%3}, {%4,%5,%6,%7}, {%8,%9}, {%0,%1,%2,%3};"
        : "+f"(c[0]), "+f"(c[1]), "+f"(c[2]), "+f"(c[3])
        : "r"(a[0]), "r"(a[1]), "r"(a[2]), "r"(a[3]), "r"(b0), "r"(b1));
}

__device__ __forceinline__ void split16(float v, __half* hi, __half* lo) {
    __half h = __float2half(v);
    *hi = h;
    *lo = __float2half(v - __half2float(h));
}

// ---------------- setup -------------------------------------------------------
__global__ void k_setup(const float* __restrict__ X) {   // 256 x 256
    int c = threadIdx.x, b = blockIdx.x;
    float s = 0.f;
    for (int r = b; r < NN; r += 256) {
        float v = X[(size_t)r * IND + c];
        __half hi, lo; split16(v, &hi, &lo);
        g_Ahi[(size_t)r * IND + c] = hi;
        g_Alo[(size_t)r * IND + c] = lo;
        s += v;
    }
    g_colpart[b * 256 + c] = s;
    int idx = b * 256 + c;
    for (int j = idx; j < SNB * SCHUNK; j += 65536) g_cnt[j] = 0;
    for (int j = idx; j < NV; j += 65536) g_cur[j] = 0;
    uint32_t* am = &g_asmax[0][0];
    if (idx < 6) am[idx] = 0;
    if (idx < C2) g_vS[idx] = 0.f;
    if (idx < 2) g_vden[idx] = 0.f;
    if (idx == 0) g_vdone = 0;
}

// ---------------- prep: weight conversions + virtual-node row ----------------
__global__ void k_prep(const float* __restrict__ W0, const float* __restrict__ W1,
                       const float* __restrict__ W2, const float* __restrict__ Wo) {
    if (blockIdx.x == 544) {
        int c = threadIdx.x;
        float s = 0.f;
        for (int p = 0; p < 256; p++) s += g_colpart[p * 256 + c];
        float v = s * (1.0f / NN);
        __half hi, lo; split16(v, &hi, &lo);
        g_Ahi[(size_t)NN * IND + c] = hi;
        g_Alo[(size_t)NN * IND + c] = lo;
        return;
    }
    int i = blockIdx.x * 256 + threadIdx.x;
    const float* W; int K, Ncol, off, loc;
    if      (i < 65536)  { W = W0; K = 256; Ncol = 256; off = 0;      loc = i; }
    else if (i < 98304)  { W = W1; K = 128; Ncol = 256; off = 65536;  loc = i - 65536; }
    else if (i < 131072) { W = W2; K = 128; Ncol = 256; off = 98304;  loc = i - 98304; }
    else if (i < WTOT)   { W = Wo; K = 128; Ncol = 64;  off = 131072; loc = i - 131072; }
    else return;
    int n = loc / K, k = loc % K;
    g_Bt[off + n * K + k] = __float2half(W[k * Ncol + n]);
}

// ---------------- CSR build ---------------------------------------------------
__global__ void k_hist(const int* __restrict__ ei) {
    int i = blockIdx.x * blockDim.x + threadIdx.x;
    int stride = gridDim.x * blockDim.x;
    for (int e = i; e < NE; e += stride)
        atomicAdd(&g_cnt[ei[NE + e]], 1);
}

__global__ void k_scan1() {        // SNB x 1024
    int b = blockIdx.x, t = threadIdx.x, lane = t & 31, w = t >> 5;
    int idx = b * SCHUNK + t;
    int v = g_cnt[idx];
    int x = v;
#pragma unroll
    for (int off = 1; off < 32; off <<= 1) {
        int y = __shfl_up_sync(0xffffffffu, x, off);
        if (lane >= off) x += y;
    }
    __shared__ int wt[32];
    if (lane == 31) wt[w] = x;
    __syncthreads();
    if (w == 0) {
        int z = wt[lane];
#pragma unroll
        for (int off = 1; off < 32; off <<= 1) {
            int y = __shfl_up_sync(0xffffffffu, z, off);
            if (lane >= off) z += y;
        }
        wt[lane] = z;
    }
    __syncthreads();
    int excl = x - v + (w ? wt[w - 1] : 0);
    g_scan[idx] = excl;
    if (t == 0) g_btot[b] = wt[31];
}

__global__ void k_scan2() {        // 1 x 64
    __shared__ int s[SNB];
    int t = threadIdx.x;
    if (t < SNB) s[t] = g_btot[t];
    __syncthreads();
    if (t == 0) {
        int acc = 0;
        for (int i = 0; i < SNB; i++) { g_boff[i] = acc; acc += s[i]; }
    }
}

__device__ __forceinline__ int rowptr_of(int i) {
    return g_scan[i] + g_boff[i >> 10];
}

__global__ void k_fill(const int* __restrict__ ei) {
    int i = blockIdx.x * blockDim.x + threadIdx.x;
    int stride = gridDim.x * blockDim.x;
    for (int e = i; e < NE; e += stride) {
        int s = ei[e];
        int d = ei[NE + e];
        int pos = rowptr_of(d) + atomicAdd(&g_cur[d], 1);
        g_srcsorted[pos] = s;
    }
}

// ---------------- HMMA GEMM: fp16 2-product (Ahi·B + Alo·B), fp32 accum ------
template<int KTOT, int NTB, bool ALPHA, bool BIAS>
__global__ void __launch_bounds__(512, 1) k_hgemm(
    const __half* __restrict__ Ahi, const __half* __restrict__ Alo,
    const __half* __restrict__ Bt,
    float* __restrict__ Cout, int M,
    const float* __restrict__ aws, const float* __restrict__ awd,
    const float* __restrict__ bias, uint32_t* __restrict__ asmax)
{
    constexpr int NCH = KTOT / 64;
    constexpr int NTW = (NTB / 2) / 8;
    constexpr int NJP = NTW / 2;
    constexpr int STAGE = 32768 + NTB * 128;

    extern __shared__ char smem[];
    uint32_t sb = smem_to_u32(smem);
    int tid = threadIdx.x, wid = tid >> 5, lane = tid & 31;
    int wm = wid >> 1, wn = wid & 1;
    int row0 = blockIdx.x * 128;

    float acc[NTW][4];
#pragma unroll
    for (int nt = 0; nt < NTW; nt++) { acc[nt][0]=0.f; acc[nt][1]=0.f; acc[nt][2]=0.f; acc[nt][3]=0.f; }

    int arow = wm * 16 + ((lane >> 3) & 1) * 8 + (lane & 7);
    uint32_t akoff = ((lane >> 4) & 1) * 16;
    int bnrow = wn * (NTB / 2) + ((lane >> 4) & 1) * 8 + (lane & 7);
    uint32_t bkoff = ((lane >> 3) & 1) * 16;

    for (int ch = 0; ch <= NCH; ch++) {
        if (ch < NCH) {
            uint32_t base = sb + (uint32_t)(ch & 1) * STAGE;
            for (int u = tid; u < 1024; u += 512) {
                int r = u >> 3, c8 = u & 7;
                size_t gidx = (size_t)(row0 + r) * KTOT + ch * 64 + c8 * 8;
                uint32_t soff = SW128((uint32_t)(r * 128 + c8 * 16));
                CP16(base + soff, Ahi + gidx);
                CP16(base + 16384 + soff, Alo + gidx);
            }
            for (int u = tid; u < NTB * 8; u += 512) {
                int r = u >> 3, c8 = u & 7;
                size_t gidx = (size_t)r * KTOT + ch * 64 + c8 * 8;
                uint32_t soff = SW128((uint32_t)(r * 128 + c8 * 16));
                CP16(base + 32768 + soff, Bt + gidx);
            }
            CPCOMMIT();
        }
        if (ch == 0) continue;
        if (ch < NCH) asm volatile("cp.async.wait_group 1;" ::: "memory");
        else         asm volatile("cp.async.wait_group 0;" ::: "memory");
        __syncthreads();
        uint32_t ab = sb + (uint32_t)((ch - 1) & 1) * STAGE;
#pragma unroll
        for (int ks = 0; ks < 4; ks++) {
            uint32_t ah[4], al[4];
            uint32_t aaddr = ab + SW128((uint32_t)(arow * 128 + ks * 32 + akoff));
            LDSM_X4(ah[0], ah[1], ah[2], ah[3], aaddr);
            LDSM_X4(al[0], al[1], al[2], al[3], aaddr + 16384);
#pragma unroll
            for (int jp = 0; jp < NJP; jp++) {
                uint32_t baddr = ab + 32768 + SW128((uint32_t)((bnrow + jp * 16) * 128 + ks * 32 + bkoff));
                uint32_t b0, b1, b2, b3;
                LDSM_X4(b0, b1, b2, b3, baddr);
                mma16816(acc[2 * jp],     ah, b0, b1);
                mma16816(acc[2 * jp],     al, b0, b1);
                mma16816(acc[2 * jp + 1], ah, b2, b3);
                mma16816(acc[2 * jp + 1], al, b2, b3);
            }
        }
        __syncthreads();
    }

    int g = lane >> 2, t = lane & 3;
    int gr0 = row0 + wm * 16 + g, gr1 = gr0 + 8;
    float pa0 = 0.f, pa1 = 0.f, pd0 = 0.f, pd1 = 0.f;
#pragma unroll
    for (int nt = 0; nt < NTW; nt++) {
        int gc = wn * (NTB / 2) + nt * 8 + t * 2;
        float c0 = acc[nt][0], c1 = acc[nt][1], c2 = acc[nt][2], c3 = acc[nt][3];
        if (BIAS) {
            float b0 = bias[gc], b1 = bias[gc + 1];
            c0 += b0; c1 += b1; c2 += b0; c3 += b1;
        }
        if (ALPHA) {
            float w0s = aws[gc], w1s = aws[gc + 1], w0d = awd[gc], w1d = awd[gc + 1];
            pa0 += c0 * w0s + c1 * w1s; pd0 += c0 * w0d + c1 * w1d;
            pa1 += c2 * w0s + c3 * w1s; pd1 += c2 * w0d + c3 * w1d;
        }
        if (gr0 < M) *(float2*)&Cout[(size_t)gr0 * NTB + gc] = make_float2(c0, c1);
        if (gr1 < M) *(float2*)&Cout[(size_t)gr1 * NTB + gc] = make_float2(c2, c3);
    }
    if (ALPHA) {
#pragma unroll
        for (int off = 1; off <= 2; off <<= 1) {
            pa0 += __shfl_xor_sync(0xffffffffu, pa0, off);
            pa1 += __shfl_xor_sync(0xffffffffu, pa1, off);
            pd0 += __shfl_xor_sync(0xffffffffu, pd0, off);
            pd1 += __shfl_xor_sync(0xffffffffu, pd1, off);
        }
        float lm = -3.4e38f;
        if (t == 0) {
            if (gr0 < M) { g_as[2 * gr0 + wn] = pa0; g_ad[2 * gr0 + wn] = pd0; lm = pa0; }
            if (gr1 < M) { g_as[2 * gr1 + wn] = pa1; g_ad[2 * gr1 + wn] = pd1; lm = fmaxf(lm, pa1); }
        }
#pragma unroll
        for (int off = 16; off; off >>= 1) lm = fmaxf(lm, __shfl_xor_sync(0xffffffffu, lm, off));
        if (lane == 0) atomicMax(asmax + wn, fkey(lm));
    }
}

// ---------------- merged vnode + node aggregation ----------------------------
#define VB 256
__global__ void k_agg(int l, const float* __restrict__ b, const float* __restrict__ gam,
                      const float* __restrict__ bet) {
    int tid = threadIdx.x, wid = tid >> 5, lane = tid & 31;
    float m0g = funkey(g_asmax[l][0]), m1g = funkey(g_asmax[l][1]);

    if (blockIdx.x < VB) {
        // ---- vnode accumulation ----
        float adv0 = g_ad[2 * NN], adv1 = g_ad[2 * NN + 1];
        float m0 = lrelu(m0g + adv0), m1 = lrelu(m1g + adv1);
        int gw = blockIdx.x * 8 + wid;
        float a0x=0,a0y=0,a0z=0,a0w=0, a1x=0,a1y=0,a1z=0,a1w=0;
        float den0 = 0.f, den1 = 0.f;
        for (int j = gw; j < NV; j += VB * 8) {
            float e0 = __expf(lrelu(g_as[2 * j] + adv0) - m0);
            float e1 = __expf(lrelu(g_as[2 * j + 1] + adv1) - m1);
            den0 += e0; den1 += e1;
            const float4* hp4 = (const float4*)(g_h + (size_t)j * C2);
            float4 f0 = hp4[lane], f1 = hp4[32 + lane];
            a0x = fmaf(e0, f0.x, a0x); a0y = fmaf(e0, f0.y, a0y);
            a0z = fmaf(e0, f0.z, a0z); a0w = fmaf(e0, f0.w, a0w);
            a1x = fmaf(e1, f1.x, a1x); a1y = fmaf(e1, f1.y, a1y);
            a1z = fmaf(e1, f1.z, a1z); a1w = fmaf(e1, f1.w, a1w);
        }
        __shared__ float buf[C2];
        __shared__ float sden[2];
        if (tid < C2) buf[tid] = 0.f;
        if (tid < 2) sden[tid] = 0.f;
        __syncthreads();
        atomicAdd(&buf[4 * lane + 0], a0x); atomicAdd(&buf[4 * lane + 1], a0y);
        atomicAdd(&buf[4 * lane + 2], a0z); atomicAdd(&buf[4 * lane + 3], a0w);
        atomicAdd(&buf[128 + 4 * lane + 0], a1x); atomicAdd(&buf[128 + 4 * lane + 1], a1y);
        atomicAdd(&buf[128 + 4 * lane + 2], a1z); atomicAdd(&buf[128 + 4 * lane + 3], a1w);
        if (lane == 0) { atomicAdd(&sden[0], den0); atomicAdd(&sden[1], den1); }
        __syncthreads();
        if (tid < C2) atomicAdd(&g_vS[tid], buf[tid]);
        if (tid < 2) atomicAdd(&g_vden[tid], sden[tid]);

        __threadfence();
        __shared__ int slast;
        if (tid == 0) slast = (atomicAdd(&g_vdone, 1) == VB - 1);
        __syncthreads();
        if (!slast) return;

        int o = tid;
        float v = 0.f;
        if (o < 128) {
            float d0 = g_vden[0] + 1e-16f, d1 = g_vden[1] + 1e-16f;
            v = 0.5f * (g_vS[o] / d0 + g_vS[HID + o] / d1) + b[o];
        }
        __shared__ float ssum[8], ssq[8];
        float ls = (o < 128) ? v : 0.f, lq = (o < 128) ? v * v : 0.f;
#pragma unroll
        for (int off = 16; off; off >>= 1) {
            ls += __shfl_xor_sync(0xffffffffu, ls, off);
            lq += __shfl_xor_sync(0xffffffffu, lq, off);
        }
        if (lane == 0) { ssum[wid] = ls; ssq[wid] = lq; }
        __syncthreads();
        float ts = ssum[0] + ssum[1] + ssum[2] + ssum[3];
        float tq = ssq[0] + ssq[1] + ssq[2] + ssq[3];
        float mu = ts * (1.0f / HID);
        float var = tq * (1.0f / HID) - mu * mu;
        if (o < 128) {
            float y = (v - mu) * rsqrtf(var + 1e-5f) * gam[o] + bet[o];
            y = 0.5f * y * (1.f + erff(y * 0.70710678118654752f));
            __half hi, lo; split16(y, &hi, &lo);
            g_Ahi[(size_t)NN * HID + o] = hi;
            g_Alo[(size_t)NN * HID + o] = lo;
        }
        __syncthreads();
        if (o < C2) g_vS[o] = 0.f;
        if (o < 2) g_vden[o] = 0.f;
        if (o == 0) g_vdone = 0;
        return;
    }

    // ---- per-node aggregation (warp per node) ----
    int i = (blockIdx.x - VB) * 8 + wid;
    if (i >= NN) return;
    float ad0 = g_ad[2 * i], ad1 = g_ad[2 * i + 1];
    float m0 = lrelu(m0g + ad0), m1 = lrelu(m1g + ad1);

    float a0x=0,a0y=0,a0z=0,a0w=0, a1x=0,a1y=0,a1z=0,a1w=0;
    float den0, den1;
    {
        float c0 = __expf(lrelu(g_as[2 * i] + ad0) - m0);
        float c1 = __expf(lrelu(g_as[2 * i + 1] + ad1) - m1);
        den0 = c0; den1 = c1;
        const float4* hp4 = (const float4*)(g_h + (size_t)i * C2);
        float4 f0 = hp4[lane], f1 = hp4[32 + lane];
        a0x = fmaf(c0, f0.x, a0x); a0y = fmaf(c0, f0.y, a0y);
        a0z = fmaf(c0, f0.z, a0z); a0w = fmaf(c0, f0.w, a0w);
        a1x = fmaf(c1, f1.x, a1x); a1y = fmaf(c1, f1.y, a1y);
        a1z = fmaf(c1, f1.z, a1z); a1w = fmaf(c1, f1.w, a1w);
        c0 = __expf(lrelu(g_as[2 * NN] + ad0) - m0);
        c1 = __expf(lrelu(g_as[2 * NN + 1] + ad1) - m1);
        den0 += c0; den1 += c1;
        const float4* hv4 = (const float4*)(g_h + (size_t)NN * C2);
        f0 = hv4[lane]; f1 = hv4[32 + lane];
        a0x = fmaf(c0, f0.x, a0x); a0y = fmaf(c0, f0.y, a0y);
        a0z = fmaf(c0, f0.z, a0z); a0w = fmaf(c0, f0.w, a0w);
        a1x = fmaf(c1, f1.x, a1x); a1y = fmaf(c1, f1.y, a1y);
        a1z = fmaf(c1, f1.z, a1z); a1w = fmaf(c1, f1.w, a1w);
    }
    int beg = rowptr_of(i), end = rowptr_of(i + 1);
    if (beg < end) {
        int s = g_srcsorted[beg];
        float as0 = g_as[2 * s], as1 = g_as[2 * s + 1];
        for (int e = beg; e < end; e++) {
            int scur = s;
            float ca0 = as0, ca1 = as1;
            if (e + 1 < end) {
                s = g_srcsorted[e + 1];
                as0 = g_as[2 * s]; as1 = g_as[2 * s + 1];
            }
            float c0 = __expf(lrelu(ca0 + ad0) - m0);
            float c1 = __expf(lrelu(ca1 + ad1) - m1);
            den0 += c0; den1 += c1;
            const float4* hp4 = (const float4*)(g_h + (size_t)scur * C2);
            float4 f0 = hp4[lane], f1 = hp4[32 + lane];
            a0x = fmaf(c0, f0.x, a0x); a0y = fmaf(c0, f0.y, a0y);
            a0z = fmaf(c0, f0.z, a0z); a0w = fmaf(c0, f0.w, a0w);
            a1x = fmaf(c1, f1.x, a1x); a1y = fmaf(c1, f1.y, a1y);
            a1z = fmaf(c1, f1.z, a1z); a1w = fmaf(c1, f1.w, a1w);
        }
    }

    float inv0 = 0.5f / (den0 + 1e-16f);
    float inv1 = 0.5f / (den1 + 1e-16f);
    float v[4];
    v[0] = a0x * inv0 + a1x * inv1;
    v[1] = a0y * inv0 + a1y * inv1;
    v[2] = a0z * inv0 + a1z * inv1;
    v[3] = a0w * inv0 + a1w * inv1;
    float lsum = 0.f, lsq = 0.f;
#pragma unroll
    for (int r = 0; r < 4; r++) {
        int o = 4 * lane + r;
        v[r] += b[o];
        lsum += v[r];
        lsq = fmaf(v[r], v[r], lsq);
    }
#pragma unroll
    for (int off = 16; off; off >>= 1) {
        lsum += __shfl_xor_sync(0xffffffffu, lsum, off);
        lsq += __shfl_xor_sync(0xffffffffu, lsq, off);
    }
    float mu = lsum * (1.0f / HID);
    float var = lsq * (1.0f / HID) - mu * mu;
    float rstd = rsqrtf(var + 1e-5f);
    __half hs[4], ls4[4];
#pragma unroll
    for (int r = 0; r < 4; r++) {
        int o = 4 * lane + r;
        float y = (v[r] - mu) * rstd * gam[o] + bet[o];
        y = 0.5f * y * (1.f + erff(y * 0.70710678118654752f));
        split16(y, &hs[r], &ls4[r]);
    }
    *(uint2*)&g_Ahi[(size_t)i * HID + 4 * lane] = *(uint2*)hs;
    *(uint2*)&g_Alo[(size_t)i * HID + 4 * lane] = *(uint2*)ls4;
}

// ---------------- host orchestration ----------------------------------------
extern "C" void kernel_launch(void* const* d_in, const int* in_sizes, int n_in,
                              void* d_out, int out_size) {
    const float* X  = (const float*)d_in[0];
    const int*   ei = (const int*)d_in[1];
    const float* W[3]   = { (const float*)d_in[3],  (const float*)d_in[9],  (const float*)d_in[15] };
    const float* a_s[3] = { (const float*)d_in[4],  (const float*)d_in[10], (const float*)d_in[16] };
    const float* a_d[3] = { (const float*)d_in[5],  (const float*)d_in[11], (const float*)d_in[17] };
    const float* bb[3]  = { (const float*)d_in[6],  (const float*)d_in[12], (const float*)d_in[18] };
    const float* gg[3]  = { (const float*)d_in[7],  (const float*)d_in[13], (const float*)d_in[19] };
    const float* be[3]  = { (const float*)d_in[8],  (const float*)d_in[14], (const float*)d_in[20] };
    const float* Wout = (const float*)d_in[21];
    const float* bout = (const float*)d_in[22];

    __half *pAhi, *pAlo, *pBt;
    float* p_h;
    uint32_t* p_am;
    cudaGetSymbolAddress((void**)&pAhi, g_Ahi);
    cudaGetSymbolAddress((void**)&pAlo, g_Alo);
    cudaGetSymbolAddress((void**)&pBt,  g_Bt);
    cudaGetSymbolAddress((void**)&p_h,  g_h);
    cudaGetSymbolAddress((void**)&p_am, g_asmax);

    const int SM256 = 2 * (32768 + 256 * 128);   // 131072
    const int SM64  = 2 * (32768 + 64 * 128);    // 81920
    cudaFuncSetAttribute(k_hgemm<256, 256, true,  false>, cudaFuncAttributeMaxDynamicSharedMemorySize, SM256);
    cudaFuncSetAttribute(k_hgemm<128, 256, true,  false>, cudaFuncAttributeMaxDynamicSharedMemorySize, SM256);
    cudaFuncSetAttribute(k_hgemm<128, 64,  false, true>,  cudaFuncAttributeMaxDynamicSharedMemorySize, SM64);

    const int NBLK = NPAD / 128;          // 391
    const int AGGB = VB + (NN + 7) / 8;   // 6506
    const int WOFF[4] = { 0, 65536, 98304, 131072 };

    k_setup<<<256, 256>>>(X);                          // idx 0
    k_prep<<<545, 256>>>(W[0], W[1], W[2], Wout);      // idx 1
    k_hist<<<1024, 256>>>(ei);                         // idx 2
    // layer-0 GEMM at idx 3 == ncu-profiled launch
    k_hgemm<256, 256, true, false><<<NBLK, 512, SM256>>>(
        pAhi, pAlo, pBt + WOFF[0], p_h, NV, a_s[0], a_d[0], nullptr, p_am + 0);
    k_scan1<<<SNB, 1024>>>();                          // idx 4
    k_scan2<<<1, 64>>>();                              // idx 5
    k_fill<<<1024, 256>>>(ei);                         // idx 6
    k_agg<<<AGGB, 256>>>(0, bb[0], gg[0], be[0]);

    for (int l = 1; l < 3; l++) {
        k_hgemm<128, 256, true, false><<<NBLK, 512, SM256>>>(
            pAhi, pAlo, pBt + WOFF[l], p_h, NV, a_s[l], a_d[l], nullptr, p_am + 2 * l);
        k_agg<<<AGGB, 256>>>(l, bb[l], gg[l], be[l]);
    }

    k_hgemm<128, 64, false, true><<<NBLK, 512, SM64>>>(
        pAhi, pAlo, pBt + WOFF[3], (float*)d_out, NN, nullptr, nullptr, bout, nullptr);
}

// round 8
// speedup vs baseline: 2.8279x; 1.2030x over previous
#include <cuda_runtime.h>
#include <cuda_fp16.h>
#include <math.h>
#include <stdint.h>

#define NN   50000
#define NV   50001
#define NPAD 50048      // 391 * 128
#define NE   400000
#define IND  256
#define HID  128
#define C2   256
#define OD   64
#define WTOT 139264
#define SCHUNK 1024
#define SNB   49

// ---------------- static device scratch -------------------------------------
__device__ __half g_Ahi[(size_t)NPAD * IND];
__device__ __half g_Alo[(size_t)NPAD * IND];
__device__ __half g_Bt[WTOT];
__device__ __half g_hh[(size_t)NV * C2];      // transformed features, fp16
__device__ float g_as[NV * 2];
__device__ float g_ad[NV * 2];
__device__ int   g_cnt[SNB * SCHUNK];
__device__ int   g_cur[NV];
__device__ int   g_scan[SNB * SCHUNK];
__device__ int   g_btot[SNB];
__device__ int   g_boff[SNB];
__device__ int   g_srcsorted[NE];
__device__ float g_colpart[256 * 256];
__device__ uint32_t g_asmax[3][2];
__device__ float g_vS[C2];
__device__ float g_vden[2];
__device__ int   g_vdone;

__device__ __forceinline__ float lrelu(float x) { return x > 0.f ? x : 0.2f * x; }

__device__ __forceinline__ uint32_t fkey(float f) {
    uint32_t b = __float_as_uint(f);
    return b ^ (uint32_t)(((int)b >> 31) | (int)0x80000000);
}
__device__ __forceinline__ float funkey(uint32_t k) {
    uint32_t b = (k & 0x80000000u) ? (k ^ 0x80000000u) : ~k;
    return __uint_as_float(b);
}

__device__ __forceinline__ uint32_t smem_to_u32(const void* p) {
    uint32_t a;
    asm("{ .reg .u64 t; cvta.to.shared.u64 t, %1; cvt.u32.u64 %0, t; }" : "=r"(a) : "l"(p));
    return a;
}

#define SW128(off) ((off) ^ (((off) >> 3) & 0x70))

#define LDSM_X4(r0, r1, r2, r3, addr) \
    asm volatile("ldmatrix.sync.aligned.m8n8.x4.shared.b16 {%0,%1,%2,%3}, [%4];" \
        : "=r"(r0), "=r"(r1), "=r"(r2), "=r"(r3) : "r"(addr))

#define CP16(s, g) asm volatile("cp.async.cg.shared.global [%0], [%1], 16;" :: "r"(s), "l"(g))
#define CPCOMMIT() asm volatile("cp.async.commit_group;" ::: "memory")

__device__ __forceinline__ void mma16816(float* c, const uint32_t* a, uint32_t b0, uint32_t b1) {
    asm volatile("mma.sync.aligned.m16n8k16.row.col.f32.f16.f16.f32 "
        "{%0,%1,%2,%3}, {%4,%5,%6,%7}, {%8,%9}, {%0,%1,%2,%3};"
        : "+f"(c[0]), "+f"(c[1]), "+f"(c[2]), "+f"(c[3])
        : "r"(a[0]), "r"(a[1]), "r"(a[2]), "r"(a[3]), "r"(b0), "r"(b1));
}

__device__ __forceinline__ void split16(float v, __half* hi, __half* lo) {
    __half h = __float2half(v);
    *hi = h;
    *lo = __float2half(v - __half2float(h));
}

// ---------------- setup: X convert (blocks 0..255) + edge hist (256..1279) ---
// g_cnt zero at entry (zero-init first call; k_scan1 re-zeroes each replay).
// g_asmax MUST be reset here (before any GEMM of this replay writes it) —
// resetting it inside k_agg races with late-scheduled consumer blocks.
__global__ void k_setup(const float* __restrict__ X, const int* __restrict__ ei) {
    if (blockIdx.x >= 256) {
        int i = (blockIdx.x - 256) * 256 + threadIdx.x;
        int stride = 1024 * 256;
        for (int e = i; e < NE; e += stride)
            atomicAdd(&g_cnt[ei[NE + e]], 1);
        return;
    }
    int c = threadIdx.x, b = blockIdx.x;
    if (b == 0 && c < 6) (&g_asmax[0][0])[c] = 0;
    float s = 0.f;
    for (int r = b; r < NN; r += 256) {
        float v = X[(size_t)r * IND + c];
        __half hi, lo; split16(v, &hi, &lo);
        g_Ahi[(size_t)r * IND + c] = hi;
        g_Alo[(size_t)r * IND + c] = lo;
        s += v;
    }
    g_colpart[b * 256 + c] = s;
}

// ---------------- prep: weight conversions + virtual-node row ----------------
__global__ void k_prep(const float* __restrict__ W0, const float* __restrict__ W1,
                       const float* __restrict__ W2, const float* __restrict__ Wo) {
    if (blockIdx.x == 544) {
        int c = threadIdx.x;
        float s = 0.f;
        for (int p = 0; p < 256; p++) s += g_colpart[p * 256 + c];
        float v = s * (1.0f / NN);
        __half hi, lo; split16(v, &hi, &lo);
        g_Ahi[(size_t)NN * IND + c] = hi;
        g_Alo[(size_t)NN * IND + c] = lo;
        return;
    }
    int i = blockIdx.x * 256 + threadIdx.x;
    const float* W; int K, Ncol, off, loc;
    if      (i < 65536)  { W = W0; K = 256; Ncol = 256; off = 0;      loc = i; }
    else if (i < 98304)  { W = W1; K = 128; Ncol = 256; off = 65536;  loc = i - 65536; }
    else if (i < 131072) { W = W2; K = 128; Ncol = 256; off = 98304;  loc = i - 98304; }
    else if (i < WTOT)   { W = Wo; K = 128; Ncol = 64;  off = 131072; loc = i - 131072; }
    else return;
    int n = loc / K, k = loc % K;
    g_Bt[off + n * K + k] = __float2half(W[k * Ncol + n]);
}

// ---------------- CSR scan (also re-zeroes g_cnt, g_cur for next replay) -----
__global__ void k_scan1() {        // SNB x 1024
    int b = blockIdx.x, t = threadIdx.x, lane = t & 31, w = t >> 5;
    int idx = b * SCHUNK + t;
    int v = g_cnt[idx];
    g_cnt[idx] = 0;
    if (idx < NV) g_cur[idx] = 0;
    int x = v;
#pragma unroll
    for (int off = 1; off < 32; off <<= 1) {
        int y = __shfl_up_sync(0xffffffffu, x, off);
        if (lane >= off) x += y;
    }
    __shared__ int wt[32];
    if (lane == 31) wt[w] = x;
    __syncthreads();
    if (w == 0) {
        int z = wt[lane];
#pragma unroll
        for (int off = 1; off < 32; off <<= 1) {
            int y = __shfl_up_sync(0xffffffffu, z, off);
            if (lane >= off) z += y;
        }
        wt[lane] = z;
    }
    __syncthreads();
    int excl = x - v + (w ? wt[w - 1] : 0);
    g_scan[idx] = excl;
    if (t == 0) g_btot[b] = wt[31];
}

__global__ void k_scan2() {        // 1 x 64
    __shared__ int s[SNB];
    int t = threadIdx.x;
    if (t < SNB) s[t] = g_btot[t];
    __syncthreads();
    if (t == 0) {
        int acc = 0;
        for (int i = 0; i < SNB; i++) { g_boff[i] = acc; acc += s[i]; }
    }
}

__device__ __forceinline__ int rowptr_of(int i) {
    return g_scan[i] + g_boff[i >> 10];
}

__global__ void k_fill(const int* __restrict__ ei) {
    int i = blockIdx.x * blockDim.x + threadIdx.x;
    int stride = gridDim.x * blockDim.x;
    for (int e = i; e < NE; e += stride) {
        int s = ei[e];
        int d = ei[NE + e];
        int pos = rowptr_of(d) + atomicAdd(&g_cur[d], 1);
        g_srcsorted[pos] = s;
    }
}

// ---------------- HMMA GEMM: fp16 2-product, 32x64 warp tiles ----------------
// 512 threads = 16 warps in 4(M) x 4(N) grid; warp = 32 rows x NTB/4 cols.
template<int KTOT, int NTB, bool ALPHA, bool HOUT>
__global__ void __launch_bounds__(512, 1) k_hgemm(
    const __half* __restrict__ Ahi, const __half* __restrict__ Alo,
    const __half* __restrict__ Bt,
    void* __restrict__ Cout, int M,
    const float* __restrict__ aws, const float* __restrict__ awd,
    const float* __restrict__ bias, uint32_t* __restrict__ asmax)
{
    constexpr int NCH = KTOT / 64;
    constexpr int NTW = (NTB / 4) / 8;
    constexpr int NJP = NTW / 2;
    constexpr int STAGE = 32768 + NTB * 128;

    extern __shared__ char smem[];
    uint32_t sb = smem_to_u32(smem);
    int tid = threadIdx.x, wid = tid >> 5, lane = tid & 31;
    int wm = wid >> 2, wn = wid & 3;
    int row0 = blockIdx.x * 128;

    float acc[2][NTW][4];
#pragma unroll
    for (int mt = 0; mt < 2; mt++)
#pragma unroll
        for (int nt = 0; nt < NTW; nt++)
#pragma unroll
            for (int j = 0; j < 4; j++) acc[mt][nt][j] = 0.f;

    int lmrow = ((lane >> 3) & 1) * 8 + (lane & 7);
    uint32_t akoff = ((lane >> 4) & 1) * 16;
    int bnrow = wn * (NTB / 4) + ((lane >> 4) & 1) * 8 + (lane & 7);
    uint32_t bkoff = ((lane >> 3) & 1) * 16;

    for (int ch = 0; ch <= NCH; ch++) {
        if (ch < NCH) {
            uint32_t base = sb + (uint32_t)(ch & 1) * STAGE;
            for (int u = tid; u < 1024; u += 512) {
                int r = u >> 3, c8 = u & 7;
                size_t gidx = (size_t)(row0 + r) * KTOT + ch * 64 + c8 * 8;
                uint32_t soff = SW128((uint32_t)(r * 128 + c8 * 16));
                CP16(base + soff, Ahi + gidx);
                CP16(base + 16384 + soff, Alo + gidx);
            }
            for (int u = tid; u < NTB * 8; u += 512) {
                int r = u >> 3, c8 = u & 7;
                size_t gidx = (size_t)r * KTOT + ch * 64 + c8 * 8;
                uint32_t soff = SW128((uint32_t)(r * 128 + c8 * 16));
                CP16(base + 32768 + soff, Bt + gidx);
            }
            CPCOMMIT();
        }
        if (ch == 0) continue;
        if (ch < NCH) asm volatile("cp.async.wait_group 1;" ::: "memory");
        else         asm volatile("cp.async.wait_group 0;" ::: "memory");
        __syncthreads();
        uint32_t ab = sb + (uint32_t)((ch - 1) & 1) * STAGE;
#pragma unroll
        for (int ks = 0; ks < 4; ks++) {
            uint32_t ah[2][4], al[2][4];
#pragma unroll
            for (int mt = 0; mt < 2; mt++) {
                uint32_t aaddr = ab + SW128((uint32_t)((wm * 32 + mt * 16 + lmrow) * 128 + ks * 32 + akoff));
                LDSM_X4(ah[mt][0], ah[mt][1], ah[mt][2], ah[mt][3], aaddr);
                LDSM_X4(al[mt][0], al[mt][1], al[mt][2], al[mt][3], aaddr + 16384);
            }
#pragma unroll
            for (int jp = 0; jp < NJP; jp++) {
                uint32_t baddr = ab + 32768 + SW128((uint32_t)((bnrow + jp * 16) * 128 + ks * 32 + bkoff));
                uint32_t b0, b1, b2, b3;
                LDSM_X4(b0, b1, b2, b3, baddr);
#pragma unroll
                for (int mt = 0; mt < 2; mt++) {
                    mma16816(acc[mt][2 * jp],     ah[mt], b0, b1);
                    mma16816(acc[mt][2 * jp],     al[mt], b0, b1);
                    mma16816(acc[mt][2 * jp + 1], ah[mt], b2, b3);
                    mma16816(acc[mt][2 * jp + 1], al[mt], b2, b3);
                }
            }
        }
        __syncthreads();
    }

    // ---- epilogue ----
    float* sAs = (float*)smem;          // [128][4]
    float* sAd = sAs + 512;             // [128][4]
    float* sMx = sAd + 512;             // [32]
    int g = lane >> 2, t = lane & 3;
#pragma unroll
    for (int mt = 0; mt < 2; mt++) {
        int r0 = wm * 32 + mt * 16 + g;
        int gr0 = row0 + r0, gr1 = gr0 + 8;
        float pa0 = 0.f, pa1 = 0.f, pd0 = 0.f, pd1 = 0.f;
#pragma unroll
        for (int nt = 0; nt < NTW; nt++) {
            int gc = wn * (NTB / 4) + nt * 8 + t * 2;
            float c0 = acc[mt][nt][0], c1 = acc[mt][nt][1];
            float c2 = acc[mt][nt][2], c3 = acc[mt][nt][3];
            if (!ALPHA) {
                float b0 = bias[gc], b1 = bias[gc + 1];
                c0 += b0; c1 += b1; c2 += b0; c3 += b1;
            }
            if (ALPHA) {
                float w0s = aws[gc], w1s = aws[gc + 1], w0d = awd[gc], w1d = awd[gc + 1];
                pa0 += c0 * w0s + c1 * w1s; pd0 += c0 * w0d + c1 * w1d;
                pa1 += c2 * w0s + c3 * w1s; pd1 += c2 * w0d + c3 * w1d;
            }
            if (HOUT) {
                __half* Ch = (__half*)Cout;
                if (gr0 < M) *(__half2*)(Ch + (size_t)gr0 * NTB + gc) = __floats2half2_rn(c0, c1);
                if (gr1 < M) *(__half2*)(Ch + (size_t)gr1 * NTB + gc) = __floats2half2_rn(c2, c3);
            } else {
                float* Cf = (float*)Cout;
                if (gr0 < M) *(float2*)(Cf + (size_t)gr0 * NTB + gc) = make_float2(c0, c1);
                if (gr1 < M) *(float2*)(Cf + (size_t)gr1 * NTB + gc) = make_float2(c2, c3);
            }
        }
        if (ALPHA) {
#pragma unroll
            for (int off = 1; off <= 2; off <<= 1) {
                pa0 += __shfl_xor_sync(0xffffffffu, pa0, off);
                pa1 += __shfl_xor_sync(0xffffffffu, pa1, off);
                pd0 += __shfl_xor_sync(0xffffffffu, pd0, off);
                pd1 += __shfl_xor_sync(0xffffffffu, pd1, off);
            }
            if (t == 0) {
                sAs[r0 * 4 + wn] = pa0; sAs[(r0 + 8) * 4 + wn] = pa1;
                sAd[r0 * 4 + wn] = pd0; sAd[(r0 + 8) * 4 + wn] = pd1;
            }
        }
    }
    if (ALPHA) {
        __syncthreads();
        float lm0 = -3.4e38f, lm1 = -3.4e38f;
        if (tid < 128) {
            int row = row0 + tid;
            float as0 = sAs[tid * 4 + 0] + sAs[tid * 4 + 1];
            float as1 = sAs[tid * 4 + 2] + sAs[tid * 4 + 3];
            float ad0 = sAd[tid * 4 + 0] + sAd[tid * 4 + 1];
            float ad1 = sAd[tid * 4 + 2] + sAd[tid * 4 + 3];
            if (row < M) {
                g_as[2 * row] = as0; g_as[2 * row + 1] = as1;
                g_ad[2 * row] = ad0; g_ad[2 * row + 1] = ad1;
                lm0 = as0; lm1 = as1;
            }
        }
#pragma unroll
        for (int off = 16; off; off >>= 1) {
            lm0 = fmaxf(lm0, __shfl_xor_sync(0xffffffffu, lm0, off));
            lm1 = fmaxf(lm1, __shfl_xor_sync(0xffffffffu, lm1, off));
        }
        if (lane == 0) { sMx[wid] = lm0; sMx[16 + wid] = lm1; }
        __syncthreads();
        if (tid == 0) {
            float m0 = -3.4e38f, m1 = -3.4e38f;
            for (int w = 0; w < 16; w++) { m0 = fmaxf(m0, sMx[w]); m1 = fmaxf(m1, sMx[16 + w]); }
            atomicMax(asmax + 0, fkey(m0));
            atomicMax(asmax + 1, fkey(m1));
        }
    }
}

// ---------------- merged vnode + node aggregation ----------------------------
#define VB 256
__global__ void k_agg(int l, const float* __restrict__ b, const float* __restrict__ gam,
                      const float* __restrict__ bet) {
    int tid = threadIdx.x, wid = tid >> 5, lane = tid & 31;
    float m0g = funkey(g_asmax[l][0]), m1g = funkey(g_asmax[l][1]);

    if (blockIdx.x < VB) {
        // ---- vnode accumulation ----
        float adv0 = g_ad[2 * NN], adv1 = g_ad[2 * NN + 1];
        float m0 = lrelu(m0g + adv0), m1 = lrelu(m1g + adv1);
        int gw = blockIdx.x * 8 + wid;
        float a0x=0,a0y=0,a0z=0,a0w=0, a1x=0,a1y=0,a1z=0,a1w=0;
        float den0 = 0.f, den1 = 0.f;
        for (int j = gw; j < NV; j += VB * 8) {
            float e0 = __expf(lrelu(g_as[2 * j] + adv0) - m0);
            float e1 = __expf(lrelu(g_as[2 * j + 1] + adv1) - m1);
            den0 += e0; den1 += e1;
            const uint2* hp = (const uint2*)(g_hh + (size_t)j * C2);
            uint2 u0 = hp[lane], u1 = hp[32 + lane];
            float2 q0 = __half22float2(*(__half2*)&u0.x);
            float2 q1 = __half22float2(*(__half2*)&u0.y);
            float2 q2 = __half22float2(*(__half2*)&u1.x);
            float2 q3 = __half22float2(*(__half2*)&u1.y);
            a0x = fmaf(e0, q0.x, a0x); a0y = fmaf(e0, q0.y, a0y);
            a0z = fmaf(e0, q1.x, a0z); a0w = fmaf(e0, q1.y, a0w);
            a1x = fmaf(e1, q2.x, a1x); a1y = fmaf(e1, q2.y, a1y);
            a1z = fmaf(e1, q3.x, a1z); a1w = fmaf(e1, q3.y, a1w);
        }
        __shared__ float buf[C2];
        __shared__ float sden[2];
        if (tid < C2) buf[tid] = 0.f;
        if (tid < 2) sden[tid] = 0.f;
        __syncthreads();
        atomicAdd(&buf[4 * lane + 0], a0x); atomicAdd(&buf[4 * lane + 1], a0y);
        atomicAdd(&buf[4 * lane + 2], a0z); atomicAdd(&buf[4 * lane + 3], a0w);
        atomicAdd(&buf[128 + 4 * lane + 0], a1x); atomicAdd(&buf[128 + 4 * lane + 1], a1y);
        atomicAdd(&buf[128 + 4 * lane + 2], a1z); atomicAdd(&buf[128 + 4 * lane + 3], a1w);
        if (lane == 0) { atomicAdd(&sden[0], den0); atomicAdd(&sden[1], den1); }
        __syncthreads();
        if (tid < C2) atomicAdd(&g_vS[tid], buf[tid]);
        if (tid < 2) atomicAdd(&g_vden[tid], sden[tid]);

        __threadfence();
        __shared__ int slast;
        if (tid == 0) slast = (atomicAdd(&g_vdone, 1) == VB - 1);
        __syncthreads();
        if (!slast) return;

        int o = tid;
        float v = 0.f;
        if (o < 128) {
            float d0 = g_vden[0] + 1e-16f, d1 = g_vden[1] + 1e-16f;
            v = 0.5f * (g_vS[o] / d0 + g_vS[HID + o] / d1) + b[o];
        }
        __shared__ float ssum[8], ssq[8];
        float ls = (o < 128) ? v : 0.f, lq = (o < 128) ? v * v : 0.f;
#pragma unroll
        for (int off = 16; off; off >>= 1) {
            ls += __shfl_xor_sync(0xffffffffu, ls, off);
            lq += __shfl_xor_sync(0xffffffffu, lq, off);
        }
        if (lane == 0) { ssum[wid] = ls; ssq[wid] = lq; }
        __syncthreads();
        float ts = ssum[0] + ssum[1] + ssum[2] + ssum[3];
        float tq = ssq[0] + ssq[1] + ssq[2] + ssq[3];
        float mu = ts * (1.0f / HID);
        float var = tq * (1.0f / HID) - mu * mu;
        if (o < 128) {
            float y = (v - mu) * rsqrtf(var + 1e-5f) * gam[o] + bet[o];
            y = 0.5f * y * (1.f + erff(y * 0.70710678118654752f));
            __half hi, lo; split16(y, &hi, &lo);
            g_Ahi[(size_t)NN * HID + o] = hi;
            g_Alo[(size_t)NN * HID + o] = lo;
        }
        __syncthreads();
        if (o < C2) g_vS[o] = 0.f;
        if (o < 2) g_vden[o] = 0.f;
        if (o == 0) g_vdone = 0;
        return;
    }

    // ---- per-node aggregation (warp per node) ----
    int i = (blockIdx.x - VB) * 8 + wid;
    if (i >= NN) return;
    float ad0 = g_ad[2 * i], ad1 = g_ad[2 * i + 1];
    float m0 = lrelu(m0g + ad0), m1 = lrelu(m1g + ad1);

    float a0x=0,a0y=0,a0z=0,a0w=0, a1x=0,a1y=0,a1z=0,a1w=0;
    float den0, den1;
    {
        float c0 = __expf(lrelu(g_as[2 * i] + ad0) - m0);
        float c1 = __expf(lrelu(g_as[2 * i + 1] + ad1) - m1);
        den0 = c0; den1 = c1;
        const uint2* hp = (const uint2*)(g_hh + (size_t)i * C2);
        uint2 u0 = hp[lane], u1 = hp[32 + lane];
        float2 q0 = __half22float2(*(__half2*)&u0.x);
        float2 q1 = __half22float2(*(__half2*)&u0.y);
        float2 q2 = __half22float2(*(__half2*)&u1.x);
        float2 q3 = __half22float2(*(__half2*)&u1.y);
        a0x = fmaf(c0, q0.x, a0x); a0y = fmaf(c0, q0.y, a0y);
        a0z = fmaf(c0, q1.x, a0z); a0w = fmaf(c0, q1.y, a0w);
        a1x = fmaf(c1, q2.x, a1x); a1y = fmaf(c1, q2.y, a1y);
        a1z = fmaf(c1, q3.x, a1z); a1w = fmaf(c1, q3.y, a1w);
        c0 = __expf(lrelu(g_as[2 * NN] + ad0) - m0);
        c1 = __expf(lrelu(g_as[2 * NN + 1] + ad1) - m1);
        den0 += c0; den1 += c1;
        const uint2* hv = (const uint2*)(g_hh + (size_t)NN * C2);
        u0 = hv[lane]; u1 = hv[32 + lane];
        q0 = __half22float2(*(__half2*)&u0.x);
        q1 = __half22float2(*(__half2*)&u0.y);
        q2 = __half22float2(*(__half2*)&u1.x);
        q3 = __half22float2(*(__half2*)&u1.y);
        a0x = fmaf(c0, q0.x, a0x); a0y = fmaf(c0, q0.y, a0y);
        a0z = fmaf(c0, q1.x, a0z); a0w = fmaf(c0, q1.y, a0w);
        a1x = fmaf(c1, q2.x, a1x); a1y = fmaf(c1, q2.y, a1y);
        a1z = fmaf(c1, q3.x, a1z); a1w = fmaf(c1, q3.y, a1w);
    }
    int beg = rowptr_of(i), end = rowptr_of(i + 1);
    if (beg < end) {
        int s = g_srcsorted[beg];
        float as0 = g_as[2 * s], as1 = g_as[2 * s + 1];
        for (int e = beg; e < end; e++) {
            int scur = s;
            float ca0 = as0, ca1 = as1;
            if (e + 1 < end) {
                s = g_srcsorted[e + 1];
                as0 = g_as[2 * s]; as1 = g_as[2 * s + 1];
            }
            float c0 = __expf(lrelu(ca0 + ad0) - m0);
            float c1 = __expf(lrelu(ca1 + ad1) - m1);
            den0 += c0; den1 += c1;
            const uint2* hp = (const uint2*)(g_hh + (size_t)scur * C2);
            uint2 u0 = hp[lane], u1 = hp[32 + lane];
            float2 q0 = __half22float2(*(__half2*)&u0.x);
            float2 q1 = __half22float2(*(__half2*)&u0.y);
            float2 q2 = __half22float2(*(__half2*)&u1.x);
            float2 q3 = __half22float2(*(__half2*)&u1.y);
            a0x = fmaf(c0, q0.x, a0x); a0y = fmaf(c0, q0.y, a0y);
            a0z = fmaf(c0, q1.x, a0z); a0w = fmaf(c0, q1.y, a0w);
            a1x = fmaf(c1, q2.x, a1x); a1y = fmaf(c1, q2.y, a1y);
            a1z = fmaf(c1, q3.x, a1z); a1w = fmaf(c1, q3.y, a1w);
        }
    }

    float inv0 = 0.5f / (den0 + 1e-16f);
    float inv1 = 0.5f / (den1 + 1e-16f);
    float v[4];
    v[0] = a0x * inv0 + a1x * inv1;
    v[1] = a0y * inv0 + a1y * inv1;
    v[2] = a0z * inv0 + a1z * inv1;
    v[3] = a0w * inv0 + a1w * inv1;
    float lsum = 0.f, lsq = 0.f;
#pragma unroll
    for (int r = 0; r < 4; r++) {
        int o = 4 * lane + r;
        v[r] += b[o];
        lsum += v[r];
        lsq = fmaf(v[r], v[r], lsq);
    }
#pragma unroll
    for (int off = 16; off; off >>= 1) {
        lsum += __shfl_xor_sync(0xffffffffu, lsum, off);
        lsq += __shfl_xor_sync(0xffffffffu, lsq, off);
    }
    float mu = lsum * (1.0f / HID);
    float var = lsq * (1.0f / HID) - mu * mu;
    float rstd = rsqrtf(var + 1e-5f);
    __half hs[4], ls4[4];
#pragma unroll
    for (int r = 0; r < 4; r++) {
        int o = 4 * lane + r;
        float y = (v[r] - mu) * rstd * gam[o] + bet[o];
        y = 0.5f * y * (1.f + erff(y * 0.70710678118654752f));
        split16(y, &hs[r], &ls4[r]);
    }
    *(uint2*)&g_Ahi[(size_t)i * HID + 4 * lane] = *(uint2*)hs;
    *(uint2*)&g_Alo[(size_t)i * HID + 4 * lane] = *(uint2*)ls4;
}

// ---------------- host orchestration ----------------------------------------
extern "C" void kernel_launch(void* const* d_in, const int* in_sizes, int n_in,
                              void* d_out, int out_size) {
    const float* X  = (const float*)d_in[0];
    const int*   ei = (const int*)d_in[1];
    const float* W[3]   = { (const float*)d_in[3],  (const float*)d_in[9],  (const float*)d_in[15] };
    const float* a_s[3] = { (const float*)d_in[4],  (const float*)d_in[10], (const float*)d_in[16] };
    const float* a_d[3] = { (const float*)d_in[5],  (const float*)d_in[11], (const float*)d_in[17] };
    const float* bb[3]  = { (const float*)d_in[6],  (const float*)d_in[12], (const float*)d_in[18] };
    const float* gg[3]  = { (const float*)d_in[7],  (const float*)d_in[13], (const float*)d_in[19] };
    const float* be[3]  = { (const float*)d_in[8],  (const float*)d_in[14], (const float*)d_in[20] };
    const float* Wout = (const float*)d_in[21];
    const float* bout = (const float*)d_in[22];

    __half *pAhi, *pAlo, *pBt, *p_hh;
    uint32_t* p_am;
    cudaGetSymbolAddress((void**)&pAhi, g_Ahi);
    cudaGetSymbolAddress((void**)&pAlo, g_Alo);
    cudaGetSymbolAddress((void**)&pBt,  g_Bt);
    cudaGetSymbolAddress((void**)&p_hh, g_hh);
    cudaGetSymbolAddress((void**)&p_am, g_asmax);

    const int SM256 = 2 * (32768 + 256 * 128);   // 131072
    const int SM64  = 2 * (32768 + 64 * 128);    // 81920
    cudaFuncSetAttribute(k_hgemm<256, 256, true,  true>,  cudaFuncAttributeMaxDynamicSharedMemorySize, SM256);
    cudaFuncSetAttribute(k_hgemm<128, 256, true,  true>,  cudaFuncAttributeMaxDynamicSharedMemorySize, SM256);
    cudaFuncSetAttribute(k_hgemm<128, 64,  false, false>, cudaFuncAttributeMaxDynamicSharedMemorySize, SM64);

    const int NBLK = NPAD / 128;          // 391
    const int AGGB = VB + (NN + 7) / 8;   // 6506
    const int WOFF[4] = { 0, 65536, 98304, 131072 };

    k_setup<<<1280, 256>>>(X, ei);                     // idx 0 (convert + hist + asmax reset)
    k_prep<<<545, 256>>>(W[0], W[1], W[2], Wout);      // idx 1
    k_scan1<<<SNB, 1024>>>();                          // idx 2
    // layer-0 GEMM at idx 3 == ncu-profiled launch
    k_hgemm<256, 256, true, true><<<NBLK, 512, SM256>>>(
        pAhi, pAlo, pBt + WOFF[0], p_hh, NV, a_s[0], a_d[0], nullptr, p_am + 0);
    k_scan2<<<1, 64>>>();                              // idx 4
    k_fill<<<1024, 256>>>(ei);                         // idx 5
    k_agg<<<AGGB, 256>>>(0, bb[0], gg[0], be[0]);      // idx 6

    for (int l = 1; l < 3; l++) {
        k_hgemm<128, 256, true, true><<<NBLK, 512, SM256>>>(
            pAhi, pAlo, pBt + WOFF[l], p_hh, NV, a_s[l], a_d[l], nullptr, p_am + 2 * l);
        k_agg<<<AGGB, 256>>>(l, bb[l], gg[l], be[l]);
    }

    k_hgemm<128, 64, false, false><<<NBLK, 512, SM64>>>(
        pAhi, pAlo, pBt + WOFF[3], (float*)d_out, NN, nullptr, nullptr, bout, nullptr);
}

// round 9
// speedup vs baseline: 2.9098x; 1.0290x over previous
#include <cuda_runtime.h>
#include <cuda_fp16.h>
#include <math.h>
#include <stdint.h>

#define NN   50000
#define NV   50001
#define NPAD 50048      // 782 * 64
#define NE   400000
#define IND  256
#define HID  128
#define C2   256
#define OD   64
#define WTOT 139264
#define SCHUNK 1024
#define SNB   49

// ---------------- static device scratch -------------------------------------
__device__ __half g_Ahi[(size_t)NPAD * IND];
__device__ __half g_Alo[(size_t)NPAD * IND];
__device__ __half g_Bt[WTOT];
__device__ __half g_hh[(size_t)NV * C2];
__device__ float g_as[NV * 2];
__device__ float g_ad[NV * 2];
__device__ int   g_cnt[SNB * SCHUNK];
__device__ int   g_cur[NV];
__device__ int   g_scan[SNB * SCHUNK];
__device__ int   g_btot[SNB];
__device__ int   g_boff[SNB];
__device__ int   g_sdone;
__device__ int   g_srcsorted[NE];
__device__ float g_colpart[256 * 256];
__device__ uint32_t g_asmax[3][2];
__device__ float g_vS[C2];
__device__ float g_vden[2];
__device__ int   g_vdone;

__device__ __forceinline__ float lrelu(float x) { return x > 0.f ? x : 0.2f * x; }

__device__ __forceinline__ uint32_t fkey(float f) {
    uint32_t b = __float_as_uint(f);
    return b ^ (uint32_t)(((int)b >> 31) | (int)0x80000000);
}
__device__ __forceinline__ float funkey(uint32_t k) {
    uint32_t b = (k & 0x80000000u) ? (k ^ 0x80000000u) : ~k;
    return __uint_as_float(b);
}

__device__ __forceinline__ uint32_t smem_to_u32(const void* p) {
    uint32_t a;
    asm("{ .reg .u64 t; cvta.to.shared.u64 t, %1; cvt.u32.u64 %0, t; }" : "=r"(a) : "l"(p));
    return a;
}

#define SW128(off) ((off) ^ (((off) >> 3) & 0x70))

#define LDSM_X4(r0, r1, r2, r3, addr) \
    asm volatile("ldmatrix.sync.aligned.m8n8.x4.shared.b16 {%0,%1,%2,%3}, [%4];" \
        : "=r"(r0), "=r"(r1), "=r"(r2), "=r"(r3) : "r"(addr))

#define CP16(s, g) asm volatile("cp.async.cg.shared.global [%0], [%1], 16;" :: "r"(s), "l"(g))
#define CPCOMMIT() asm volatile("cp.async.commit_group;" ::: "memory")

__device__ __forceinline__ void mma16816(float* c, const uint32_t* a, uint32_t b0, uint32_t b1) {
    asm volatile("mma.sync.aligned.m16n8k16.row.col.f32.f16.f16.f32 "
        "{%0,%1,%2,%3}, {%4,%5,%6,%7}, {%8,%9}, {%0,%1,%2,%3};"
        : "+f"(c[0]), "+f"(c[1]), "+f"(c[2]), "+f"(c[3])
        : "r"(a[0]), "r"(a[1]), "r"(a[2]), "r"(a[3]), "r"(b0), "r"(b1));
}

__device__ __forceinline__ void split16(float v, __half* hi, __half* lo) {
    __half h = __float2half(v);
    *hi = h;
    *lo = __float2half(v - __half2float(h));
}

// ---------------- setup: X convert + edge hist + asmax reset -----------------
__global__ void k_setup(const float* __restrict__ X, const int* __restrict__ ei) {
    if (blockIdx.x >= 256) {
        int i = (blockIdx.x - 256) * 256 + threadIdx.x;
        int stride = 1024 * 256;
        for (int e = i; e < NE; e += stride)
            atomicAdd(&g_cnt[ei[NE + e]], 1);
        return;
    }
    int c = threadIdx.x, b = blockIdx.x;
    if (b == 0 && c < 6) (&g_asmax[0][0])[c] = 0;
    float s = 0.f;
    for (int r = b; r < NN; r += 256) {
        float v = X[(size_t)r * IND + c];
        __half hi, lo; split16(v, &hi, &lo);
        g_Ahi[(size_t)r * IND + c] = hi;
        g_Alo[(size_t)r * IND + c] = lo;
        s += v;
    }
    g_colpart[b * 256 + c] = s;
}

// ---------------- prep: weight conversions + virtual-node row ----------------
__global__ void k_prep(const float* __restrict__ W0, const float* __restrict__ W1,
                       const float* __restrict__ W2, const float* __restrict__ Wo) {
    if (blockIdx.x == 544) {
        int c = threadIdx.x;
        float s = 0.f;
        for (int p = 0; p < 256; p++) s += g_colpart[p * 256 + c];
        float v = s * (1.0f / NN);
        __half hi, lo; split16(v, &hi, &lo);
        g_Ahi[(size_t)NN * IND + c] = hi;
        g_Alo[(size_t)NN * IND + c] = lo;
        return;
    }
    int i = blockIdx.x * 256 + threadIdx.x;
    const float* W; int K, Ncol, off, loc;
    if      (i < 65536)  { W = W0; K = 256; Ncol = 256; off = 0;      loc = i; }
    else if (i < 98304)  { W = W1; K = 128; Ncol = 256; off = 65536;  loc = i - 65536; }
    else if (i < 131072) { W = W2; K = 128; Ncol = 256; off = 98304;  loc = i - 98304; }
    else if (i < WTOT)   { W = Wo; K = 128; Ncol = 64;  off = 131072; loc = i - 131072; }
    else return;
    int n = loc / K, k = loc % K;
    g_Bt[off + n * K + k] = __float2half(W[k * Ncol + n]);
}

// ---------------- CSR scan (re-zeroes g_cnt/g_cur; last block does level-2) --
__global__ void k_scan1() {        // SNB x 1024
    int b = blockIdx.x, t = threadIdx.x, lane = t & 31, w = t >> 5;
    int idx = b * SCHUNK + t;
    int v = g_cnt[idx];
    g_cnt[idx] = 0;
    if (idx < NV) g_cur[idx] = 0;
    int x = v;
#pragma unroll
    for (int off = 1; off < 32; off <<= 1) {
        int y = __shfl_up_sync(0xffffffffu, x, off);
        if (lane >= off) x += y;
    }
    __shared__ int wt[32];
    if (lane == 31) wt[w] = x;
    __syncthreads();
    if (w == 0) {
        int z = wt[lane];
#pragma unroll
        for (int off = 1; off < 32; off <<= 1) {
            int y = __shfl_up_sync(0xffffffffu, z, off);
            if (lane >= off) z += y;
        }
        wt[lane] = z;
    }
    __syncthreads();
    int excl = x - v + (w ? wt[w - 1] : 0);
    g_scan[idx] = excl;
    if (t == 0) {
        g_btot[b] = wt[31];
        __threadfence();
        if (atomicAdd(&g_sdone, 1) == SNB - 1) {   // last block: level-2 prefix
            int acc = 0;
            for (int i = 0; i < SNB; i++) { g_boff[i] = acc; acc += g_btot[i]; }
            g_sdone = 0;
        }
    }
}

__device__ __forceinline__ int rowptr_of(int i) {
    return g_scan[i] + g_boff[i >> 10];
}

__global__ void k_fill(const int* __restrict__ ei) {
    int i = blockIdx.x * blockDim.x + threadIdx.x;
    int stride = gridDim.x * blockDim.x;
    for (int e = i; e < NE; e += stride) {
        int s = ei[e];
        int d = ei[NE + e];
        int pos = rowptr_of(d) + atomicAdd(&g_cur[d], 1);
        g_srcsorted[pos] = s;
    }
}

// ---------------- HMMA GEMM: fp16 2-product, 64-row blocks, 2 CTAs/SM --------
// 256 threads = 8 warps in 2(M) x 4(N); warp = 32 rows x NTB/4 cols.
template<int KTOT, int NTB, bool ALPHA, bool HOUT>
__global__ void __launch_bounds__(256, 2) k_hgemm(
    const __half* __restrict__ Ahi, const __half* __restrict__ Alo,
    const __half* __restrict__ Bt,
    void* __restrict__ Cout, int M,
    const float* __restrict__ aws, const float* __restrict__ awd,
    const float* __restrict__ bias, uint32_t* __restrict__ asmax)
{
    constexpr int NCH = KTOT / 64;
    constexpr int NTW = (NTB / 4) / 8;
    constexpr int NJP = NTW / 2;
    constexpr int STAGE = 16384 + NTB * 128;

    extern __shared__ char smem[];
    uint32_t sb = smem_to_u32(smem);
    int tid = threadIdx.x, wid = tid >> 5, lane = tid & 31;
    int wm = wid >> 2, wn = wid & 3;
    int row0 = blockIdx.x * 64;

    float acc[2][NTW][4];
#pragma unroll
    for (int mt = 0; mt < 2; mt++)
#pragma unroll
        for (int nt = 0; nt < NTW; nt++)
#pragma unroll
            for (int j = 0; j < 4; j++) acc[mt][nt][j] = 0.f;

    int lmrow = ((lane >> 3) & 1) * 8 + (lane & 7);
    uint32_t akoff = ((lane >> 4) & 1) * 16;
    int bnrow = wn * (NTB / 4) + ((lane >> 4) & 1) * 8 + (lane & 7);
    uint32_t bkoff = ((lane >> 3) & 1) * 16;

    for (int ch = 0; ch <= NCH; ch++) {
        if (ch < NCH) {
            uint32_t base = sb + (uint32_t)(ch & 1) * STAGE;
            for (int u = tid; u < 512; u += 256) {
                int r = u >> 3, c8 = u & 7;
                size_t gidx = (size_t)(row0 + r) * KTOT + ch * 64 + c8 * 8;
                uint32_t soff = SW128((uint32_t)(r * 128 + c8 * 16));
                CP16(base + soff, Ahi + gidx);
                CP16(base + 8192 + soff, Alo + gidx);
            }
            for (int u = tid; u < NTB * 8; u += 256) {
                int r = u >> 3, c8 = u & 7;
                size_t gidx = (size_t)r * KTOT + ch * 64 + c8 * 8;
                uint32_t soff = SW128((uint32_t)(r * 128 + c8 * 16));
                CP16(base + 16384 + soff, Bt + gidx);
            }
            CPCOMMIT();
        }
        if (ch == 0) continue;
        if (ch < NCH) asm volatile("cp.async.wait_group 1;" ::: "memory");
        else         asm volatile("cp.async.wait_group 0;" ::: "memory");
        __syncthreads();
        uint32_t ab = sb + (uint32_t)((ch - 1) & 1) * STAGE;
#pragma unroll
        for (int ks = 0; ks < 4; ks++) {
            uint32_t ah[2][4], al[2][4];
#pragma unroll
            for (int mt = 0; mt < 2; mt++) {
                uint32_t aaddr = ab + SW128((uint32_t)((wm * 32 + mt * 16 + lmrow) * 128 + ks * 32 + akoff));
                LDSM_X4(ah[mt][0], ah[mt][1], ah[mt][2], ah[mt][3], aaddr);
                LDSM_X4(al[mt][0], al[mt][1], al[mt][2], al[mt][3], aaddr + 8192);
            }
#pragma unroll
            for (int jp = 0; jp < NJP; jp++) {
                uint32_t baddr = ab + 16384 + SW128((uint32_t)((bnrow + jp * 16) * 128 + ks * 32 + bkoff));
                uint32_t b0, b1, b2, b3;
                LDSM_X4(b0, b1, b2, b3, baddr);
#pragma unroll
                for (int mt = 0; mt < 2; mt++) {
                    mma16816(acc[mt][2 * jp],     ah[mt], b0, b1);
                    mma16816(acc[mt][2 * jp],     al[mt], b0, b1);
                    mma16816(acc[mt][2 * jp + 1], ah[mt], b2, b3);
                    mma16816(acc[mt][2 * jp + 1], al[mt], b2, b3);
                }
            }
        }
        __syncthreads();
    }

    // ---- epilogue ----
    float* sAs = (float*)smem;          // [64][4]
    float* sAd = sAs + 256;             // [64][4]
    float* sMx = sAd + 256;             // [16]
    int g = lane >> 2, t = lane & 3;
#pragma unroll
    for (int mt = 0; mt < 2; mt++) {
        int r0 = wm * 32 + mt * 16 + g;
        int gr0 = row0 + r0, gr1 = gr0 + 8;
        float pa0 = 0.f, pa1 = 0.f, pd0 = 0.f, pd1 = 0.f;
#pragma unroll
        for (int nt = 0; nt < NTW; nt++) {
            int gc = wn * (NTB / 4) + nt * 8 + t * 2;
            float c0 = acc[mt][nt][0], c1 = acc[mt][nt][1];
            float c2 = acc[mt][nt][2], c3 = acc[mt][nt][3];
            if (!ALPHA) {
                float b0 = bias[gc], b1 = bias[gc + 1];
                c0 += b0; c1 += b1; c2 += b0; c3 += b1;
            }
            if (ALPHA) {
                float w0s = aws[gc], w1s = aws[gc + 1], w0d = awd[gc], w1d = awd[gc + 1];
                pa0 += c0 * w0s + c1 * w1s; pd0 += c0 * w0d + c1 * w1d;
                pa1 += c2 * w0s + c3 * w1s; pd1 += c2 * w0d + c3 * w1d;
            }
            if (HOUT) {
                __half* Ch = (__half*)Cout;
                if (gr0 < M) *(__half2*)(Ch + (size_t)gr0 * NTB + gc) = __floats2half2_rn(c0, c1);
                if (gr1 < M) *(__half2*)(Ch + (size_t)gr1 * NTB + gc) = __floats2half2_rn(c2, c3);
            } else {
                float* Cf = (float*)Cout;
                if (gr0 < M) *(float2*)(Cf + (size_t)gr0 * NTB + gc) = make_float2(c0, c1);
                if (gr1 < M) *(float2*)(Cf + (size_t)gr1 * NTB + gc) = make_float2(c2, c3);
            }
        }
        if (ALPHA) {
#pragma unroll
            for (int off = 1; off <= 2; off <<= 1) {
                pa0 += __shfl_xor_sync(0xffffffffu, pa0, off);
                pa1 += __shfl_xor_sync(0xffffffffu, pa1, off);
                pd0 += __shfl_xor_sync(0xffffffffu, pd0, off);
                pd1 += __shfl_xor_sync(0xffffffffu, pd1, off);
            }
            if (t == 0) {
                sAs[r0 * 4 + wn] = pa0; sAs[(r0 + 8) * 4 + wn] = pa1;
                sAd[r0 * 4 + wn] = pd0; sAd[(r0 + 8) * 4 + wn] = pd1;
            }
        }
    }
    if (ALPHA) {
        __syncthreads();
        float lm0 = -3.4e38f, lm1 = -3.4e38f;
        if (tid < 64) {
            int row = row0 + tid;
            float as0 = sAs[tid * 4 + 0] + sAs[tid * 4 + 1];
            float as1 = sAs[tid * 4 + 2] + sAs[tid * 4 + 3];
            float ad0 = sAd[tid * 4 + 0] + sAd[tid * 4 + 1];
            float ad1 = sAd[tid * 4 + 2] + sAd[tid * 4 + 3];
            if (row < M) {
                g_as[2 * row] = as0; g_as[2 * row + 1] = as1;
                g_ad[2 * row] = ad0; g_ad[2 * row + 1] = ad1;
                lm0 = as0; lm1 = as1;
            }
        }
#pragma unroll
        for (int off = 16; off; off >>= 1) {
            lm0 = fmaxf(lm0, __shfl_xor_sync(0xffffffffu, lm0, off));
            lm1 = fmaxf(lm1, __shfl_xor_sync(0xffffffffu, lm1, off));
        }
        if (lane == 0 && wid < 2) { sMx[wid] = lm0; sMx[8 + wid] = lm1; }
        __syncthreads();
        if (tid == 0) {
            float m0 = fmaxf(sMx[0], sMx[1]);
            float m1 = fmaxf(sMx[8], sMx[9]);
            atomicMax(asmax + 0, fkey(m0));
            atomicMax(asmax + 1, fkey(m1));
        }
    }
}

// ---------------- merged vnode + node aggregation ----------------------------
#define VB 256
__global__ void k_agg(int l, const float* __restrict__ b, const float* __restrict__ gam,
                      const float* __restrict__ bet) {
    int tid = threadIdx.x, wid = tid >> 5, lane = tid & 31;
    float m0g = funkey(g_asmax[l][0]), m1g = funkey(g_asmax[l][1]);

    if (blockIdx.x < VB) {
        float adv0 = g_ad[2 * NN], adv1 = g_ad[2 * NN + 1];
        float m0 = lrelu(m0g + adv0), m1 = lrelu(m1g + adv1);
        int gw = blockIdx.x * 8 + wid;
        float a0x=0,a0y=0,a0z=0,a0w=0, a1x=0,a1y=0,a1z=0,a1w=0;
        float den0 = 0.f, den1 = 0.f;
        for (int j = gw; j < NV; j += VB * 8) {
            float e0 = __expf(lrelu(g_as[2 * j] + adv0) - m0);
            float e1 = __expf(lrelu(g_as[2 * j + 1] + adv1) - m1);
            den0 += e0; den1 += e1;
            const uint2* hp = (const uint2*)(g_hh + (size_t)j * C2);
            uint2 u0 = hp[lane], u1 = hp[32 + lane];
            float2 q0 = __half22float2(*(__half2*)&u0.x);
            float2 q1 = __half22float2(*(__half2*)&u0.y);
            float2 q2 = __half22float2(*(__half2*)&u1.x);
            float2 q3 = __half22float2(*(__half2*)&u1.y);
            a0x = fmaf(e0, q0.x, a0x); a0y = fmaf(e0, q0.y, a0y);
            a0z = fmaf(e0, q1.x, a0z); a0w = fmaf(e0, q1.y, a0w);
            a1x = fmaf(e1, q2.x, a1x); a1y = fmaf(e1, q2.y, a1y);
            a1z = fmaf(e1, q3.x, a1z); a1w = fmaf(e1, q3.y, a1w);
        }
        __shared__ float buf[C2];
        __shared__ float sden[2];
        if (tid < C2) buf[tid] = 0.f;
        if (tid < 2) sden[tid] = 0.f;
        __syncthreads();
        atomicAdd(&buf[4 * lane + 0], a0x); atomicAdd(&buf[4 * lane + 1], a0y);
        atomicAdd(&buf[4 * lane + 2], a0z); atomicAdd(&buf[4 * lane + 3], a0w);
        atomicAdd(&buf[128 + 4 * lane + 0], a1x); atomicAdd(&buf[128 + 4 * lane + 1], a1y);
        atomicAdd(&buf[128 + 4 * lane + 2], a1z); atomicAdd(&buf[128 + 4 * lane + 3], a1w);
        if (lane == 0) { atomicAdd(&sden[0], den0); atomicAdd(&sden[1], den1); }
        __syncthreads();
        if (tid < C2) atomicAdd(&g_vS[tid], buf[tid]);
        if (tid < 2) atomicAdd(&g_vden[tid], sden[tid]);

        __threadfence();
        __shared__ int slast;
        if (tid == 0) slast = (atomicAdd(&g_vdone, 1) == VB - 1);
        __syncthreads();
        if (!slast) return;

        int o = tid;
        float v = 0.f;
        if (o < 128) {
            float d0 = g_vden[0] + 1e-16f, d1 = g_vden[1] + 1e-16f;
            v = 0.5f * (g_vS[o] / d0 + g_vS[HID + o] / d1) + b[o];
        }
        __shared__ float ssum[8], ssq[8];
        float ls = (o < 128) ? v : 0.f, lq = (o < 128) ? v * v : 0.f;
#pragma unroll
        for (int off = 16; off; off >>= 1) {
            ls += __shfl_xor_sync(0xffffffffu, ls, off);
            lq += __shfl_xor_sync(0xffffffffu, lq, off);
        }
        if (lane == 0) { ssum[wid] = ls; ssq[wid] = lq; }
        __syncthreads();
        float ts = ssum[0] + ssum[1] + ssum[2] + ssum[3];
        float tq = ssq[0] + ssq[1] + ssq[2] + ssq[3];
        float mu = ts * (1.0f / HID);
        float var = tq * (1.0f / HID) - mu * mu;
        if (o < 128) {
            float y = (v - mu) * rsqrtf(var + 1e-5f) * gam[o] + bet[o];
            y = 0.5f * y * (1.f + erff(y * 0.70710678118654752f));
            __half hi, lo; split16(y, &hi, &lo);
            g_Ahi[(size_t)NN * HID + o] = hi;
            g_Alo[(size_t)NN * HID + o] = lo;
        }
        __syncthreads();
        if (o < C2) g_vS[o] = 0.f;
        if (o < 2) g_vden[o] = 0.f;
        if (o == 0) g_vdone = 0;
        return;
    }

    int i = (blockIdx.x - VB) * 8 + wid;
    if (i >= NN) return;
    float ad0 = g_ad[2 * i], ad1 = g_ad[2 * i + 1];
    float m0 = lrelu(m0g + ad0), m1 = lrelu(m1g + ad1);

    float a0x=0,a0y=0,a0z=0,a0w=0, a1x=0,a1y=0,a1z=0,a1w=0;
    float den0, den1;
    {
        float c0 = __expf(lrelu(g_as[2 * i] + ad0) - m0);
        float c1 = __expf(lrelu(g_as[2 * i + 1] + ad1) - m1);
        den0 = c0; den1 = c1;
        const uint2* hp = (const uint2*)(g_hh + (size_t)i * C2);
        uint2 u0 = hp[lane], u1 = hp[32 + lane];
        float2 q0 = __half22float2(*(__half2*)&u0.x);
        float2 q1 = __half22float2(*(__half2*)&u0.y);
        float2 q2 = __half22float2(*(__half2*)&u1.x);
        float2 q3 = __half22float2(*(__half2*)&u1.y);
        a0x = fmaf(c0, q0.x, a0x); a0y = fmaf(c0, q0.y, a0y);
        a0z = fmaf(c0, q1.x, a0z); a0w = fmaf(c0, q1.y, a0w);
        a1x = fmaf(c1, q2.x, a1x); a1y = fmaf(c1, q2.y, a1y);
        a1z = fmaf(c1, q3.x, a1z); a1w = fmaf(c1, q3.y, a1w);
        c0 = __expf(lrelu(g_as[2 * NN] + ad0) - m0);
        c1 = __expf(lrelu(g_as[2 * NN + 1] + ad1) - m1);
        den0 += c0; den1 += c1;
        const uint2* hv = (const uint2*)(g_hh + (size_t)NN * C2);
        u0 = hv[lane]; u1 = hv[32 + lane];
        q0 = __half22float2(*(__half2*)&u0.x);
        q1 = __half22float2(*(__half2*)&u0.y);
        q2 = __half22float2(*(__half2*)&u1.x);
        q3 = __half22float2(*(__half2*)&u1.y);
        a0x = fmaf(c0, q0.x, a0x); a0y = fmaf(c0, q0.y, a0y);
        a0z = fmaf(c0, q1.x, a0z); a0w = fmaf(c0, q1.y, a0w);
        a1x = fmaf(c1, q2.x, a1x); a1y = fmaf(c1, q2.y, a1y);
        a1z = fmaf(c1, q3.x, a1z); a1w = fmaf(c1, q3.y, a1w);
    }
    int beg = rowptr_of(i), end = rowptr_of(i + 1);
    if (beg < end) {
        int s = g_srcsorted[beg];
        float as0 = g_as[2 * s], as1 = g_as[2 * s + 1];
        for (int e = beg; e < end; e++) {
            int scur = s;
            float ca0 = as0, ca1 = as1;
            if (e + 1 < end) {
                s = g_srcsorted[e + 1];
                as0 = g_as[2 * s]; as1 = g_as[2 * s + 1];
            }
            float c0 = __expf(lrelu(ca0 + ad0) - m0);
            float c1 = __expf(lrelu(ca1 + ad1) - m1);
            den0 += c0; den1 += c1;
            const uint2* hp = (const uint2*)(g_hh + (size_t)scur * C2);
            uint2 u0 = hp[lane], u1 = hp[32 + lane];
            float2 q0 = __half22float2(*(__half2*)&u0.x);
            float2 q1 = __half22float2(*(__half2*)&u0.y);
            float2 q2 = __half22float2(*(__half2*)&u1.x);
            float2 q3 = __half22float2(*(__half2*)&u1.y);
            a0x = fmaf(c0, q0.x, a0x); a0y = fmaf(c0, q0.y, a0y);
            a0z = fmaf(c0, q1.x, a0z); a0w = fmaf(c0, q1.y, a0w);
            a1x = fmaf(c1, q2.x, a1x); a1y = fmaf(c1, q2.y, a1y);
            a1z = fmaf(c1, q3.x, a1z); a1w = fmaf(c1, q3.y, a1w);
        }
    }

    float inv0 = 0.5f / (den0 + 1e-16f);
    float inv1 = 0.5f / (den1 + 1e-16f);
    float v[4];
    v[0] = a0x * inv0 + a1x * inv1;
    v[1] = a0y * inv0 + a1y * inv1;
    v[2] = a0z * inv0 + a1z * inv1;
    v[3] = a0w * inv0 + a1w * inv1;
    float lsum = 0.f, lsq = 0.f;
#pragma unroll
    for (int r = 0; r < 4; r++) {
        int o = 4 * lane + r;
        v[r] += b[o];
        lsum += v[r];
        lsq = fmaf(v[r], v[r], lsq);
    }
#pragma unroll
    for (int off = 16; off; off >>= 1) {
        lsum += __shfl_xor_sync(0xffffffffu, lsum, off);
        lsq += __shfl_xor_sync(0xffffffffu, lsq, off);
    }
    float mu = lsum * (1.0f / HID);
    float var = lsq * (1.0f / HID) - mu * mu;
    float rstd = rsqrtf(var + 1e-5f);
    __half hs[4], ls4[4];
#pragma unroll
    for (int r = 0; r < 4; r++) {
        int o = 4 * lane + r;
        float y = (v[r] - mu) * rstd * gam[o] + bet[o];
        y = 0.5f * y * (1.f + erff(y * 0.70710678118654752f));
        split16(y, &hs[r], &ls4[r]);
    }
    *(uint2*)&g_Ahi[(size_t)i * HID + 4 * lane] = *(uint2*)hs;
    *(uint2*)&g_Alo[(size_t)i * HID + 4 * lane] = *(uint2*)ls4;
}

// ---------------- host orchestration ----------------------------------------
extern "C" void kernel_launch(void* const* d_in, const int* in_sizes, int n_in,
                              void* d_out, int out_size) {
    const float* X  = (const float*)d_in[0];
    const int*   ei = (const int*)d_in[1];
    const float* W[3]   = { (const float*)d_in[3],  (const float*)d_in[9],  (const float*)d_in[15] };
    const float* a_s[3] = { (const float*)d_in[4],  (const float*)d_in[10], (const float*)d_in[16] };
    const float* a_d[3] = { (const float*)d_in[5],  (const float*)d_in[11], (const float*)d_in[17] };
    const float* bb[3]  = { (const float*)d_in[6],  (const float*)d_in[12], (const float*)d_in[18] };
    const float* gg[3]  = { (const float*)d_in[7],  (const float*)d_in[13], (const float*)d_in[19] };
    const float* be[3]  = { (const float*)d_in[8],  (const float*)d_in[14], (const float*)d_in[20] };
    const float* Wout = (const float*)d_in[21];
    const float* bout = (const float*)d_in[22];

    __half *pAhi, *pAlo, *pBt, *p_hh;
    uint32_t* p_am;
    cudaGetSymbolAddress((void**)&pAhi, g_Ahi);
    cudaGetSymbolAddress((void**)&pAlo, g_Alo);
    cudaGetSymbolAddress((void**)&pBt,  g_Bt);
    cudaGetSymbolAddress((void**)&p_hh, g_hh);
    cudaGetSymbolAddress((void**)&p_am, g_asmax);

    const int SM256 = 2 * (16384 + 256 * 128);   // 98304
    const int SM64  = 2 * (16384 + 64 * 128);    // 49152
    cudaFuncSetAttribute(k_hgemm<256, 256, true,  true>,  cudaFuncAttributeMaxDynamicSharedMemorySize, SM256);
    cudaFuncSetAttribute(k_hgemm<128, 256, true,  true>,  cudaFuncAttributeMaxDynamicSharedMemorySize, SM256);
    cudaFuncSetAttribute(k_hgemm<128, 64,  false, false>, cudaFuncAttributeMaxDynamicSharedMemorySize, SM64);

    const int NBLK = NPAD / 64;           // 782
    const int AGGB = VB + (NN + 7) / 8;   // 6506
    const int WOFF[4] = { 0, 65536, 98304, 131072 };

    k_setup<<<1280, 256>>>(X, ei);                     // idx 0
    k_prep<<<545, 256>>>(W[0], W[1], W[2], Wout);      // idx 1
    k_scan1<<<SNB, 1024>>>();                          // idx 2 (incl. level-2)
    // layer-0 GEMM at idx 3 == ncu-profiled launch
    k_hgemm<256, 256, true, true><<<NBLK, 256, SM256>>>(
        pAhi, pAlo, pBt + WOFF[0], p_hh, NV, a_s[0], a_d[0], nullptr, p_am + 0);
    k_fill<<<1024, 256>>>(ei);                         // idx 4
    k_agg<<<AGGB, 256>>>(0, bb[0], gg[0], be[0]);      // idx 5

    for (int l = 1; l < 3; l++) {
        k_hgemm<128, 256, true, true><<<NBLK, 256, SM256>>>(
            pAhi, pAlo, pBt + WOFF[l], p_hh, NV, a_s[l], a_d[l], nullptr, p_am + 2 * l);
        k_agg<<<AGGB, 256>>>(l, bb[l], gg[l], be[l]);
    }

    k_hgemm<128, 64, false, false><<<NBLK, 256, SM64>>>(
        pAhi, pAlo, pBt + WOFF[3], (float*)d_out, NN, nullptr, nullptr, bout, nullptr);
}